// round 6
// baseline (speedup 1.0000x reference)
#include <cuda_runtime.h>
#include <math.h>
#include <stdint.h>

#define BB      8
#define NHEADS  8
#define HD      32
#define NN      1024
#define CDIM    256
#define TABLE_SZ 3969
#define CPBH    512

// ---------------- scratch (bf16 hi/lo word layouts) -------------------------
// Q/K: [(b*8+h)*1024 + n]*16 + dpair   (low16 = even d)
// V  : [(b*8+h)*32 + d]*512 + n/2      (low16 = even n)  -- transposed
__device__ __align__(16) uint32_t g_q2h[BB * NHEADS * NN * 16];
__device__ __align__(16) uint32_t g_q2l[BB * NHEADS * NN * 16];
__device__ __align__(16) uint32_t g_kh [BB * NHEADS * NN * 16];
__device__ __align__(16) uint32_t g_kl [BB * NHEADS * NN * 16];
__device__ __align__(16) uint32_t g_vth[BB * NHEADS * HD * (NN / 2)];
__device__ __align__(16) uint32_t g_vtl[BB * NHEADS * HD * (NN / 2)];
__device__ __align__(16) uint32_t g_bias[NHEADS * NN * (NN / 2)];    // bf16x2
// pre-split operand planes: [row][K/2] word layout
__device__ __align__(16) uint32_t g_xh[BB * NN * (CDIM / 2)];
__device__ __align__(16) uint32_t g_xl[BB * NN * (CDIM / 2)];
__device__ __align__(16) uint32_t g_wqh[3 * CDIM * (CDIM / 2)];
__device__ __align__(16) uint32_t g_wql[3 * CDIM * (CDIM / 2)];
__device__ __align__(16) uint32_t g_wph[CDIM * (CDIM / 2)];
__device__ __align__(16) uint32_t g_wpl[CDIM * (CDIM / 2)];
__device__ __align__(16) uint32_t g_aoh[BB * NN * (CDIM / 2)];
__device__ __align__(16) uint32_t g_aol[BB * NN * (CDIM / 2)];
__device__ float g_tab[NHEADS * TABLE_SZ];

// ---------------- bf16 helpers ----------------------------------------------
__device__ __forceinline__ uint32_t bf16x2(float lo, float hi) {
    uint32_t d;
    asm("cvt.rn.bf16x2.f32 %0, %1, %2;" : "=r"(d) : "f"(hi), "f"(lo));
    return d;
}
__device__ __forceinline__ void bfsplit2(float x0, float x1, uint32_t &hi, uint32_t &lo) {
    uint32_t h = bf16x2(x0, x1);
    float r0 = x0 - __uint_as_float(h << 16);
    float r1 = x1 - __uint_as_float(h & 0xffff0000u);
    hi = h;
    lo = bf16x2(r0, r1);
}
__device__ __forceinline__ void mma_bf16(float c[4],
                                         uint32_t a0, uint32_t a1, uint32_t a2, uint32_t a3,
                                         uint32_t b0, uint32_t b1) {
    asm volatile(
        "mma.sync.aligned.m16n8k16.row.col.f32.bf16.bf16.f32 "
        "{%0,%1,%2,%3}, {%4,%5,%6,%7}, {%8,%9}, {%0,%1,%2,%3};"
        : "+f"(c[0]), "+f"(c[1]), "+f"(c[2]), "+f"(c[3])
        : "r"(a0), "r"(a1), "r"(a2), "r"(a3), "r"(b0), "r"(b1));
}
__device__ __forceinline__ void cp16(uint32_t dst, const void* src) {
    asm volatile("cp.async.cg.shared.global [%0], [%1], 16;" :: "r"(dst), "l"(src));
}

// ---------------- f32 -> hi/lo plane converter -------------------------------
__global__ __launch_bounds__(256) void conv_split(const float* __restrict__ src,
                                                  uint32_t* __restrict__ dh,
                                                  uint32_t* __restrict__ dl,
                                                  int npairs) {
    int i = blockIdx.x * blockDim.x + threadIdx.x;     // handles pairs 2i, 2i+1
    if (2 * i + 1 < npairs) {
        float4 v = *(const float4*)&src[4 * i];
        uint32_t h0, l0, h1, l1;
        bfsplit2(v.x, v.y, h0, l0);
        bfsplit2(v.z, v.w, h1, l1);
        *(uint2*)&dh[2 * i] = make_uint2(h0, h1);
        *(uint2*)&dl[2 * i] = make_uint2(l0, l1);
    }
}

// ---------------- CPB MLP ----------------------------------------------------
__global__ void cpb_kernel(const float* __restrict__ coords,
                           const float* __restrict__ fc1w, const float* __restrict__ fc1b,
                           const float* __restrict__ fc2w, const float* __restrict__ fc2b) {
    int t = blockIdx.x;
    float c0 = coords[t * 2 + 0];
    float c1 = coords[t * 2 + 1];
    float acc[NHEADS];
#pragma unroll
    for (int h = 0; h < NHEADS; h++) acc[h] = 0.f;
    for (int j = threadIdx.x; j < CPBH; j += blockDim.x) {
        float hv = fmaxf(c0 * fc1w[j * 2] + c1 * fc1w[j * 2 + 1] + fc1b[j], 0.f);
#pragma unroll
        for (int h = 0; h < NHEADS; h++) acc[h] += hv * fc2w[h * CPBH + j];
    }
    __shared__ float red[4][NHEADS];
    int lane = threadIdx.x & 31, warp = threadIdx.x >> 5;
#pragma unroll
    for (int h = 0; h < NHEADS; h++)
        for (int o = 16; o; o >>= 1) acc[h] += __shfl_xor_sync(0xffffffffu, acc[h], o);
    if (lane == 0)
#pragma unroll
        for (int h = 0; h < NHEADS; h++) red[warp][h] = acc[h];
    __syncthreads();
    if (threadIdx.x < NHEADS) {
        float s = fc2b[threadIdx.x];
        for (int w = 0; w < 4; w++) s += red[w][threadIdx.x];
        g_tab[threadIdx.x * TABLE_SZ + t] = s;
    }
}

// ---------------- bias expand: g_bias[h][n][m/2] = bf16x2 --------------------
__global__ __launch_bounds__(256) void bias_expand(const int* __restrict__ rpi) {
    __shared__ float tab_s[TABLE_SZ];
    int h = blockIdx.x >> 6;
    int chunk = blockIdx.x & 63;
    for (int i = threadIdx.x; i < TABLE_SZ; i += 256) tab_s[i] = g_tab[h * TABLE_SZ + i];
    __syncthreads();
    for (int i = threadIdx.x; i < 16 * 512; i += 256) {
        int nl = i >> 9, mw = i & 511;
        int n = chunk * 16 + nl;
        int2 id = *(const int2*)&rpi[(size_t)n * NN + 2 * mw];
        g_bias[((size_t)h * NN + n) * 512 + mw] = bf16x2(tab_s[id.x], tab_s[id.y]);
    }
}

// ==================== GEMM mainloop (shared pattern) ==========================
// 128x64 tile, 256 threads, warps 4x2, warp tile 32x32, BK=32 (16 words),
// double-buffered cp.async from pre-split planes.
// Buffer layout (words): Ah[0,2560) Al[2560,5120) Wh[5120,6400) Wl[6400,7680)
#define GBUF 7680

#define GEMM_MAINLOOP(AHP, ALP, WHP, WLP, KDIM)                                     \
    const int tid = threadIdx.x, lane = tid & 31, warp = tid >> 5;                  \
    const int wm = (warp >> 1) * 32, wn = (warp & 1) * 32;                          \
    const int r = lane >> 2, c = lane & 3;                                          \
    const int NT = (KDIM) / 32;                                                     \
    float acc[2][4][4];                                                             \
    _Pragma("unroll")                                                               \
    for (int mt = 0; mt < 2; mt++)                                                  \
        _Pragma("unroll")                                                           \
        for (int nt = 0; nt < 4; nt++)                                              \
            _Pragma("unroll")                                                       \
            for (int q = 0; q < 4; q++) acc[mt][nt][q] = 0.f;                       \
    auto g_issue = [&](int t, int buf) {                                            \
        uint32_t s0 = (uint32_t)__cvta_generic_to_shared(smg + buf * GBUF);         \
        const int kw = t * 16;                                                      \
        _Pragma("unroll")                                                           \
        for (int i = 0; i < 4; i++) {                                               \
            int v = tid + i * 256;                                                  \
            int plane = v >> 9, rem = v & 511, row = rem >> 2, q = (rem & 3) * 4;   \
            const uint32_t* src = (plane ? (ALP) : (AHP)) +                         \
                (size_t)(bm + row) * ((KDIM) >> 1) + kw + q;                        \
            cp16(s0 + (plane * 2560 + row * 20 + q) * 4, src);                      \
        }                                                                           \
        _Pragma("unroll")                                                           \
        for (int i = 0; i < 2; i++) {                                               \
            int v = tid + i * 256;                                                  \
            int plane = v >> 8, rem = v & 255, row = rem >> 2, q = (rem & 3) * 4;   \
            const uint32_t* src = (plane ? (WLP) : (WHP)) +                         \
                (size_t)(bn + row) * ((KDIM) >> 1) + kw + q;                        \
            cp16(s0 + (5120 + plane * 1280 + row * 20 + q) * 4, src);               \
        }                                                                           \
    };                                                                              \
    g_issue(0, 0);                                                                  \
    asm volatile("cp.async.commit_group;");                                         \
    for (int t = 0; t < NT; t++) {                                                  \
        __syncthreads();                                                            \
        if (t + 1 < NT) {                                                           \
            g_issue(t + 1, (t + 1) & 1);                                            \
            asm volatile("cp.async.commit_group;");                                 \
            asm volatile("cp.async.wait_group 1;");                                 \
        } else {                                                                    \
            asm volatile("cp.async.wait_group 0;");                                 \
        }                                                                           \
        __syncthreads();                                                            \
        const uint32_t* Ahb = smg + (t & 1) * GBUF;                                 \
        const uint32_t* Alb = Ahb + 2560;                                           \
        const uint32_t* Whb = Ahb + 5120;                                           \
        const uint32_t* Wlb = Ahb + 6400;                                           \
        _Pragma("unroll")                                                           \
        for (int kt = 0; kt < 2; kt++) {                                            \
            uint32_t ah[2][4], al[2][4];                                            \
            _Pragma("unroll")                                                       \
            for (int mt = 0; mt < 2; mt++) {                                        \
                int r0 = (wm + mt * 16 + r) * 20 + kt * 8 + c;                      \
                int r1 = r0 + 8 * 20;                                               \
                ah[mt][0] = Ahb[r0];     al[mt][0] = Alb[r0];                       \
                ah[mt][1] = Ahb[r1];     al[mt][1] = Alb[r1];                       \
                ah[mt][2] = Ahb[r0 + 4]; al[mt][2] = Alb[r0 + 4];                   \
                ah[mt][3] = Ahb[r1 + 4]; al[mt][3] = Alb[r1 + 4];                   \
            }                                                                       \
            _Pragma("unroll")                                                       \
            for (int nt = 0; nt < 4; nt++) {                                        \
                int w0 = (wn + nt * 8 + r) * 20 + kt * 8 + c;                       \
                uint32_t bh0 = Whb[w0], bh1 = Whb[w0 + 4];                          \
                uint32_t bl0 = Wlb[w0], bl1 = Wlb[w0 + 4];                          \
                _Pragma("unroll")                                                   \
                for (int mt = 0; mt < 2; mt++) {                                    \
                    mma_bf16(acc[mt][nt], ah[mt][0], ah[mt][1], ah[mt][2], ah[mt][3], bh0, bh1); \
                    mma_bf16(acc[mt][nt], al[mt][0], al[mt][1], al[mt][2], al[mt][3], bh0, bh1); \
                    mma_bf16(acc[mt][nt], ah[mt][0], ah[mt][1], ah[mt][2], ah[mt][3], bl0, bl1); \
                }                                                                   \
            }                                                                       \
        }                                                                           \
    }

// ---------------- fused qkv GEMM + l2norm + split -> word layouts ------------
__global__ __launch_bounds__(256, 2) void gemm_qkv_fused(
        const float* __restrict__ bias,
        const float* __restrict__ qe, const float* __restrict__ temp) {
    extern __shared__ uint32_t smg[];
    const int bm = blockIdx.y * 128, bn = blockIdx.x * 64;
    GEMM_MAINLOOP(g_xh, g_xl, g_wqh, g_wql, CDIM)

    // ---- fused epilogue: bias, per-head l2norm, split, store word layouts ----
    const int col_base = bn + wn;
    const int region = col_base >> 8;             // 0=q, 1=k, 2=v
    const int head = (col_base >> 5) & 7;
    float scale_h = 0.f, qe0[4], qe1[4];
    if (region == 0) {
        scale_h = log1pf(expf(temp[head])) * logf(1024.0f);
#pragma unroll
        for (int nt = 0; nt < 4; nt++) {
            qe0[nt] = qe[head * HD + nt * 8 + 2 * c];
            qe1[nt] = qe[head * HD + nt * 8 + 2 * c + 1];
        }
    }
#pragma unroll
    for (int mt = 0; mt < 2; mt++) {
#pragma unroll
        for (int half = 0; half < 2; half++) {
            int row = bm + wm + mt * 16 + r + half * 8;
            int bq = row >> 10, n = row & 1023;
            float v0[4], v1[4];
#pragma unroll
            for (int nt = 0; nt < 4; nt++) {
                int cg = col_base + nt * 8 + 2 * c;
                v0[nt] = acc[mt][nt][half * 2]     + bias[cg];
                v1[nt] = acc[mt][nt][half * 2 + 1] + bias[cg + 1];
            }
            if (region < 2) {
                float ss = 0.f;
#pragma unroll
                for (int nt = 0; nt < 4; nt++) ss += v0[nt] * v0[nt] + v1[nt] * v1[nt];
                ss += __shfl_xor_sync(0xffffffffu, ss, 1);
                ss += __shfl_xor_sync(0xffffffffu, ss, 2);
                float inv = 1.f / fmaxf(sqrtf(ss), 1e-12f);
                size_t base = ((size_t)(bq * 8 + head) * NN + n) * 16;
#pragma unroll
                for (int nt = 0; nt < 4; nt++) {
                    float a = v0[nt] * inv, bv = v1[nt] * inv;
                    if (region == 0) {
                        a  = (a  + qe0[nt]) * scale_h;
                        bv = (bv + qe1[nt]) * scale_h;
                    }
                    uint32_t hh, ll;
                    bfsplit2(a, bv, hh, ll);
                    size_t w = base + nt * 4 + c;
                    if (region == 0) { g_q2h[w] = hh; g_q2l[w] = ll; }
                    else             { g_kh[w]  = hh; g_kl[w]  = ll; }
                }
            } else {
                size_t bh = (size_t)(bq * 8 + head);
                int np = n >> 1;
                bool evenr = ((r & 1) == 0);
#pragma unroll
                for (int nt = 0; nt < 4; nt++) {
                    float ge = __shfl_xor_sync(0xffffffffu, v0[nt], 4);
                    float go = __shfl_xor_sync(0xffffffffu, v1[nt], 4);
                    int dloc = nt * 8 + 2 * c;
                    float p0, p1; int d;
                    if (evenr) { p0 = v0[nt]; p1 = ge;     d = dloc; }
                    else       { p0 = go;     p1 = v1[nt]; d = dloc + 1; }
                    uint32_t hh, ll;
                    bfsplit2(p0, p1, hh, ll);
                    size_t w = (bh * HD + d) * 512 + np;
                    g_vth[w] = hh; g_vtl[w] = ll;
                }
            }
        }
    }
}

// ---------------- proj GEMM (pre-split planes -> f32 out) --------------------
__global__ __launch_bounds__(256, 2) void gemm_proj(const float* __restrict__ bias,
                                                    float* __restrict__ C) {
    extern __shared__ uint32_t smg[];
    const int bm = blockIdx.y * 128, bn = blockIdx.x * 64;
    GEMM_MAINLOOP(g_aoh, g_aol, g_wph, g_wpl, CDIM)
#pragma unroll
    for (int mt = 0; mt < 2; mt++) {
        int row0 = bm + wm + mt * 16 + r;
        int row1 = row0 + 8;
#pragma unroll
        for (int nt = 0; nt < 4; nt++) {
            int n = bn + wn + nt * 8 + 2 * c;
            float b0 = bias[n], b1 = bias[n + 1];
            *(float2*)&C[(size_t)row0 * CDIM + n] = make_float2(acc[mt][nt][0] + b0, acc[mt][nt][1] + b1);
            *(float2*)&C[(size_t)row1 * CDIM + n] = make_float2(acc[mt][nt][2] + b0, acc[mt][nt][3] + b1);
        }
    }
}

// ---------------- attention: 256 threads, 128 q-rows, cp.async dbuf ----------
#define ABUF 4864   // words: Kh 1280 | Kl 1280 | Vh 1152 | Vl 1152

__global__ __launch_bounds__(256, 2) void attn_tc() {
    extern __shared__ uint32_t smw[];

    const int n0 = blockIdx.x * 128;
    const int h  = blockIdx.y;
    const int b  = blockIdx.z;
    const int tid = threadIdx.x, lane = tid & 31, warp = tid >> 5;
    const int r = lane >> 2, c = lane & 3;
    const size_t bh = (size_t)(b * NHEADS + h);

    const uint32_t* kh_g  = g_kh  + bh * NN * 16;
    const uint32_t* kl_g  = g_kl  + bh * NN * 16;
    const uint32_t* vth_g = g_vth + bh * HD * 512;
    const uint32_t* vtl_g = g_vtl + bh * HD * 512;

    auto issue = [&](int kt, int buf) {
        uint32_t s0 = (uint32_t)__cvta_generic_to_shared(smw + buf * ABUF);
#pragma unroll
        for (int i = 0; i < 2; i++) {
            int v = tid + i * 256;
            int plane = v >> 8, rem = v & 255;
            int row = rem >> 2, cq = (rem & 3) * 4;
            const uint32_t* src = (plane ? kl_g : kh_g) + (size_t)(kt * 64 + row) * 16 + cq;
            cp16(s0 + (plane * 1280 + row * 20 + cq) * 4, src);
        }
#pragma unroll
        for (int i = 0; i < 2; i++) {
            int v = tid + i * 256;
            int plane = v >> 8, rem = v & 255;
            int d = rem >> 3, cq = (rem & 7) * 4;
            const uint32_t* src = (plane ? vtl_g : vth_g) + (size_t)d * 512 + kt * 32 + cq;
            cp16(s0 + (2560 + plane * 1152 + d * 36 + cq) * 4, src);
        }
    };

    issue(0, 0);
    asm volatile("cp.async.commit_group;");

    // Q fragments (LDG overlaps with first cp.async)
    const int nr = n0 + warp * 16 + r;
    const uint32_t* qh_g = g_q2h + bh * NN * 16;
    const uint32_t* ql_g = g_q2l + bh * NN * 16;
    uint32_t qh[2][4], ql[2][4];
#pragma unroll
    for (int ks = 0; ks < 2; ks++) {
        qh[ks][0] = qh_g[(size_t)nr * 16 + ks * 8 + c];
        qh[ks][1] = qh_g[(size_t)(nr + 8) * 16 + ks * 8 + c];
        qh[ks][2] = qh_g[(size_t)nr * 16 + ks * 8 + 4 + c];
        qh[ks][3] = qh_g[(size_t)(nr + 8) * 16 + ks * 8 + 4 + c];
        ql[ks][0] = ql_g[(size_t)nr * 16 + ks * 8 + c];
        ql[ks][1] = ql_g[(size_t)(nr + 8) * 16 + ks * 8 + c];
        ql[ks][2] = ql_g[(size_t)nr * 16 + ks * 8 + 4 + c];
        ql[ks][3] = ql_g[(size_t)(nr + 8) * 16 + ks * 8 + 4 + c];
    }

    const uint32_t* b0p = g_bias + ((size_t)h * NN + nr) * 512;
    const uint32_t* b1p = b0p + 8 * 512;

    float O[4][4] = {};
    float ml0 = -1e30f, ml1 = -1e30f, ll0 = 0.f, ll1 = 0.f;

    for (int kt = 0; kt < 16; kt++) {
        __syncthreads();
        if (kt < 15) {
            issue(kt + 1, (kt + 1) & 1);
            asm volatile("cp.async.commit_group;");
            asm volatile("cp.async.wait_group 1;");
        } else {
            asm volatile("cp.async.wait_group 0;");
        }
        __syncthreads();

        const uint32_t* Khb = smw + (kt & 1) * ABUF;
        const uint32_t* Klb = Khb + 1280;
        const uint32_t* Vhb = Khb + 2560;
        const uint32_t* Vlb = Khb + 3712;

        // bias loads issued now, consumed after the MMAs (latency hidden)
        uint32_t bw0[8], bw1[8];
#pragma unroll
        for (int j = 0; j < 8; j++) {
            bw0[j] = b0p[kt * 32 + j * 4 + c];
            bw1[j] = b1p[kt * 32 + j * 4 + c];
        }

        // ---- S = Q K^T (3-plane bf16), accumulate from 0 ----
        float sc[8][4] = {};
#pragma unroll
        for (int j = 0; j < 8; j++) {
            int rowb = (j * 8 + r) * 20;
#pragma unroll
            for (int ks = 0; ks < 2; ks++) {
                uint32_t bh0 = Khb[rowb + ks * 8 + c], bh1 = Khb[rowb + ks * 8 + 4 + c];
                uint32_t bl0 = Klb[rowb + ks * 8 + c], bl1 = Klb[rowb + ks * 8 + 4 + c];
                mma_bf16(sc[j], qh[ks][0], qh[ks][1], qh[ks][2], qh[ks][3], bh0, bh1);
                mma_bf16(sc[j], ql[ks][0], ql[ks][1], ql[ks][2], ql[ks][3], bh0, bh1);
                mma_bf16(sc[j], qh[ks][0], qh[ks][1], qh[ks][2], qh[ks][3], bl0, bl1);
            }
        }
        // add relative-position bias
#pragma unroll
        for (int j = 0; j < 8; j++) {
            sc[j][0] += __uint_as_float(bw0[j] << 16);
            sc[j][1] += __uint_as_float(bw0[j] & 0xffff0000u);
            sc[j][2] += __uint_as_float(bw1[j] << 16);
            sc[j][3] += __uint_as_float(bw1[j] & 0xffff0000u);
        }

        // ---- online softmax ----
        float mx0 = -1e30f, mx1 = -1e30f;
#pragma unroll
        for (int j = 0; j < 8; j++) {
            mx0 = fmaxf(mx0, fmaxf(sc[j][0], sc[j][1]));
            mx1 = fmaxf(mx1, fmaxf(sc[j][2], sc[j][3]));
        }
        mx0 = fmaxf(mx0, __shfl_xor_sync(0xffffffffu, mx0, 1));
        mx0 = fmaxf(mx0, __shfl_xor_sync(0xffffffffu, mx0, 2));
        mx1 = fmaxf(mx1, __shfl_xor_sync(0xffffffffu, mx1, 1));
        mx1 = fmaxf(mx1, __shfl_xor_sync(0xffffffffu, mx1, 2));
        float mn0 = fmaxf(ml0, mx0), mn1 = fmaxf(ml1, mx1);
        float a0 = __expf(ml0 - mn0), a1 = __expf(ml1 - mn1);
        float s0 = 0.f, s1 = 0.f;
        uint32_t phr[8], phr8[8], plr[8], plr8[8];
#pragma unroll
        for (int j = 0; j < 8; j++) {
            float p0 = __expf(sc[j][0] - mn0), p1 = __expf(sc[j][1] - mn0);
            float p2 = __expf(sc[j][2] - mn1), p3 = __expf(sc[j][3] - mn1);
            s0 += p0 + p1; s1 += p2 + p3;
            bfsplit2(p0, p1, phr[j],  plr[j]);
            bfsplit2(p2, p3, phr8[j], plr8[j]);
        }
        s0 += __shfl_xor_sync(0xffffffffu, s0, 1);
        s0 += __shfl_xor_sync(0xffffffffu, s0, 2);
        s1 += __shfl_xor_sync(0xffffffffu, s1, 1);
        s1 += __shfl_xor_sync(0xffffffffu, s1, 2);
        ll0 = ll0 * a0 + s0; ll1 = ll1 * a1 + s1;
        ml0 = mn0; ml1 = mn1;
#pragma unroll
        for (int jd = 0; jd < 4; jd++) {
            O[jd][0] *= a0; O[jd][1] *= a0;
            O[jd][2] *= a1; O[jd][3] *= a1;
        }

        // ---- O += P @ V (register-chained P, 3-term) ----
#pragma unroll
        for (int kk = 0; kk < 4; kk++) {
            uint32_t a0h = phr[2 * kk],     a1h = phr8[2 * kk];
            uint32_t a2h = phr[2 * kk + 1], a3h = phr8[2 * kk + 1];
            uint32_t a0l = plr[2 * kk],     a1l = plr8[2 * kk];
            uint32_t a2l = plr[2 * kk + 1], a3l = plr8[2 * kk + 1];
#pragma unroll
            for (int jd = 0; jd < 4; jd++) {
                int w0 = (jd * 8 + r) * 36 + kk * 8 + c;
                uint32_t vh0 = Vhb[w0], vh1 = Vhb[w0 + 4];
                uint32_t vl0 = Vlb[w0], vl1 = Vlb[w0 + 4];
                mma_bf16(O[jd], a0h, a1h, a2h, a3h, vh0, vh1);
                mma_bf16(O[jd], a0l, a1l, a2l, a3l, vh0, vh1);
                mma_bf16(O[jd], a0h, a1h, a2h, a3h, vl0, vl1);
            }
        }
    }

    // ---- epilogue: normalize + split -> hi/lo planes for proj ----
    float i0 = 1.f / ll0, i1 = 1.f / ll1;
    size_t base0 = (size_t)(b * NN + nr) * 128 + h * 16;
    size_t base1 = (size_t)(b * NN + nr + 8) * 128 + h * 16;
#pragma unroll
    for (int jd = 0; jd < 4; jd++) {
        uint32_t hh, ll;
        bfsplit2(O[jd][0] * i0, O[jd][1] * i0, hh, ll);
        g_aoh[base0 + jd * 4 + c] = hh;
        g_aol[base0 + jd * 4 + c] = ll;
        bfsplit2(O[jd][2] * i1, O[jd][3] * i1, hh, ll);
        g_aoh[base1 + jd * 4 + c] = hh;
        g_aol[base1 + jd * 4 + c] = ll;
    }
}

// ---------------- launch ------------------------------------------------------
extern "C" void kernel_launch(void* const* d_in, const int* in_sizes, int n_in,
                              void* d_out, int out_size) {
    int s = (n_in >= 15) ? 0 : -2;
    const float* x       = (const float*)d_in[0];
    const int*   rpi     = (const int*)  d_in[3 + s];
    const float* coords  = (const float*)d_in[4 + s];
    const float* qkv_w   = (const float*)d_in[5 + s];
    const float* qkv_b   = (const float*)d_in[6 + s];
    const float* qe      = (const float*)d_in[7 + s];
    const float* temp    = (const float*)d_in[8 + s];
    const float* proj_w  = (const float*)d_in[9 + s];
    const float* proj_b  = (const float*)d_in[10 + s];
    const float* fc1w    = (const float*)d_in[11 + s];
    const float* fc1b    = (const float*)d_in[12 + s];
    const float* fc2w    = (const float*)d_in[13 + s];
    const float* fc2b    = (const float*)d_in[14 + s];
    float* out = (float*)d_out;

    uint32_t *p_xh, *p_xl, *p_wqh, *p_wql, *p_wph, *p_wpl;
    cudaGetSymbolAddress((void**)&p_xh,  g_xh);
    cudaGetSymbolAddress((void**)&p_xl,  g_xl);
    cudaGetSymbolAddress((void**)&p_wqh, g_wqh);
    cudaGetSymbolAddress((void**)&p_wql, g_wql);
    cudaGetSymbolAddress((void**)&p_wph, g_wph);
    cudaGetSymbolAddress((void**)&p_wpl, g_wpl);

    // pre-split operands into bf16 hi/lo planes
    conv_split<<<(BB * NN * 128 / 2 + 255) / 256, 256>>>(x, p_xh, p_xl, BB * NN * 128);
    conv_split<<<(768 * 128 / 2 + 255) / 256, 256>>>(qkv_w, p_wqh, p_wql, 768 * 128);
    conv_split<<<(CDIM * 128 / 2 + 255) / 256, 256>>>(proj_w, p_wph, p_wpl, CDIM * 128);

    cpb_kernel<<<TABLE_SZ, 128>>>(coords, fc1w, fc1b, fc2w, fc2b);
    bias_expand<<<NHEADS * 64, 256>>>(rpi);

    size_t gemm_smem = 2 * GBUF * sizeof(uint32_t);   // 61.4 KB
    cudaFuncSetAttribute(gemm_qkv_fused, cudaFuncAttributeMaxDynamicSharedMemorySize, (int)gemm_smem);
    cudaFuncSetAttribute(gemm_proj, cudaFuncAttributeMaxDynamicSharedMemorySize, (int)gemm_smem);

    gemm_qkv_fused<<<dim3(768 / 64, (BB * NN) / 128), 256, gemm_smem>>>(qkv_b, qe, temp);

    {
        size_t smem = 2 * ABUF * sizeof(uint32_t);    // 38.9 KB
        cudaFuncSetAttribute(attn_tc, cudaFuncAttributeMaxDynamicSharedMemorySize, (int)smem);
        attn_tc<<<dim3(8, NHEADS, BB), 256, smem>>>();
    }

    gemm_proj<<<dim3(CDIM / 64, (BB * NN) / 128), 256, gemm_smem>>>(proj_b, out);
}

// round 7
// speedup vs baseline: 1.0370x; 1.0370x over previous
#include <cuda_runtime.h>
#include <math.h>
#include <stdint.h>

#define BB      8
#define NHEADS  8
#define HD      32
#define NN      1024
#define CDIM    256
#define TABLE_SZ 3969
#define CPBH    512

// ---------------- scratch (bf16 hi/lo word layouts) -------------------------
// Q/K: [(b*8+h)*1024 + n]*16 + dpair   (low16 = even d)
// V  : [(b*8+h)*32 + d]*512 + n/2      (low16 = even n)  -- transposed
__device__ __align__(16) uint32_t g_q2h[BB * NHEADS * NN * 16];
__device__ __align__(16) uint32_t g_q2l[BB * NHEADS * NN * 16];
__device__ __align__(16) uint32_t g_kh [BB * NHEADS * NN * 16];
__device__ __align__(16) uint32_t g_kl [BB * NHEADS * NN * 16];
__device__ __align__(16) uint32_t g_vth[BB * NHEADS * HD * (NN / 2)];
__device__ __align__(16) uint32_t g_vtl[BB * NHEADS * HD * (NN / 2)];
__device__ __align__(16) uint32_t g_bias[NHEADS * NN * (NN / 2)];    // bf16x2
__device__ float g_tab[NHEADS * TABLE_SZ];
__device__ float g_ao [BB * NN * CDIM];

// ---------------- bf16 helpers ----------------------------------------------
__device__ __forceinline__ uint32_t bf16x2(float lo, float hi) {
    uint32_t d;
    asm("cvt.rn.bf16x2.f32 %0, %1, %2;" : "=r"(d) : "f"(hi), "f"(lo));
    return d;
}
__device__ __forceinline__ void bfsplit2(float x0, float x1, uint32_t &hi, uint32_t &lo) {
    uint32_t h = bf16x2(x0, x1);
    float r0 = x0 - __uint_as_float(h << 16);
    float r1 = x1 - __uint_as_float(h & 0xffff0000u);
    hi = h;
    lo = bf16x2(r0, r1);
}
__device__ __forceinline__ void mma_bf16(float c[4],
                                         uint32_t a0, uint32_t a1, uint32_t a2, uint32_t a3,
                                         uint32_t b0, uint32_t b1) {
    asm volatile(
        "mma.sync.aligned.m16n8k16.row.col.f32.bf16.bf16.f32 "
        "{%0,%1,%2,%3}, {%4,%5,%6,%7}, {%8,%9}, {%0,%1,%2,%3};"
        : "+f"(c[0]), "+f"(c[1]), "+f"(c[2]), "+f"(c[3])
        : "r"(a0), "r"(a1), "r"(a2), "r"(a3), "r"(b0), "r"(b1));
}
__device__ __forceinline__ void cp16(uint32_t dst, const void* src) {
    asm volatile("cp.async.cg.shared.global [%0], [%1], 16;" :: "r"(dst), "l"(src));
}

// ---------------- CPB MLP (SMEM-staged weights, warp-per-entry) --------------
__global__ __launch_bounds__(256) void cpb_kernel(const float* __restrict__ coords,
                                                  const float* __restrict__ fc1w,
                                                  const float* __restrict__ fc1b,
                                                  const float* __restrict__ fc2w,
                                                  const float* __restrict__ fc2b) {
    __shared__ float s_w1[CPBH * 2];
    __shared__ float s_b1[CPBH];
    __shared__ float s_w2[NHEADS * CPBH];
    const int tid = threadIdx.x;
    for (int i = tid; i < CPBH * 2; i += 256) s_w1[i] = fc1w[i];
    for (int i = tid; i < CPBH; i += 256) s_b1[i] = fc1b[i];
    for (int i = tid; i < NHEADS * CPBH; i += 256) s_w2[i] = fc2w[i];
    __syncthreads();
    const int warp = tid >> 5, lane = tid & 31;
#pragma unroll
    for (int e = 0; e < 4; e++) {
        int t = blockIdx.x * 32 + warp * 4 + e;
        if (t >= TABLE_SZ) continue;
        float c0 = coords[2 * t], c1 = coords[2 * t + 1];
        float acc[NHEADS];
#pragma unroll
        for (int h = 0; h < NHEADS; h++) acc[h] = 0.f;
#pragma unroll 4
        for (int j = lane; j < CPBH; j += 32) {
            float hv = fmaxf(c0 * s_w1[2 * j] + c1 * s_w1[2 * j + 1] + s_b1[j], 0.f);
#pragma unroll
            for (int h = 0; h < NHEADS; h++) acc[h] += hv * s_w2[h * CPBH + j];
        }
#pragma unroll
        for (int h = 0; h < NHEADS; h++) {
#pragma unroll
            for (int o = 16; o; o >>= 1) acc[h] += __shfl_xor_sync(0xffffffffu, acc[h], o);
            if (lane == 0) g_tab[h * TABLE_SZ + t] = acc[h] + fc2b[h];
        }
    }
}

// ---------------- bias expand: g_bias[h][n][m/2] = bf16x2 --------------------
__global__ __launch_bounds__(256) void bias_expand(const int* __restrict__ rpi) {
    __shared__ float tab_s[TABLE_SZ];
    int h = blockIdx.x >> 6;
    int chunk = blockIdx.x & 63;
    for (int i = threadIdx.x; i < TABLE_SZ; i += 256) tab_s[i] = g_tab[h * TABLE_SZ + i];
    __syncthreads();
    for (int i = threadIdx.x; i < 16 * 512; i += 256) {
        int nl = i >> 9, mw = i & 511;
        int n = chunk * 16 + nl;
        int2 id = *(const int2*)&rpi[(size_t)n * NN + 2 * mw];
        g_bias[((size_t)h * NN + n) * 512 + mw] = bf16x2(tab_s[id.x], tab_s[id.y]);
    }
}

// ---------------- fused qkv GEMM + l2norm + split -> word layouts ------------
// 128x64 tile, 256 threads, warps 4x2, warp tile 32x32, BK=32; inline convert.
__global__ __launch_bounds__(256) void gemm_qkv_fused(
        const float* __restrict__ A, const float* __restrict__ W,
        const float* __restrict__ bias,
        const float* __restrict__ qe, const float* __restrict__ temp) {
    extern __shared__ uint32_t smg[];
    uint32_t* Ah = smg;               // [128][20]
    uint32_t* Al = Ah + 128 * 20;
    uint32_t* Wh = Al + 128 * 20;     // [64][20]
    uint32_t* Wl = Wh + 64 * 20;
    const int bm = blockIdx.y * 128, bn = blockIdx.x * 64;
    const int tid = threadIdx.x, lane = tid & 31, warp = tid >> 5;
    const int wm = (warp >> 1) * 32, wn = (warp & 1) * 32;
    const int r = lane >> 2, c = lane & 3;
    const int K = CDIM;

    float acc[2][4][4];
#pragma unroll
    for (int mt = 0; mt < 2; mt++)
#pragma unroll
        for (int nt = 0; nt < 4; nt++)
#pragma unroll
            for (int q = 0; q < 4; q++) acc[mt][nt][q] = 0.f;

    for (int k0 = 0; k0 < K; k0 += 32) {
#pragma unroll
        for (int i = 0; i < 4; i++) {
            int v = tid + i * 256;
            int row = v >> 3, kq = (v & 7) * 4;
            float4 a4 = *(const float4*)&A[(size_t)(bm + row) * K + k0 + kq];
            uint32_t h, l;
            bfsplit2(a4.x, a4.y, h, l);
            Ah[row * 20 + (kq >> 1)] = h;  Al[row * 20 + (kq >> 1)] = l;
            bfsplit2(a4.z, a4.w, h, l);
            Ah[row * 20 + (kq >> 1) + 1] = h;  Al[row * 20 + (kq >> 1) + 1] = l;
        }
#pragma unroll
        for (int i = 0; i < 2; i++) {
            int v = tid + i * 256;
            int row = v >> 3, kq = (v & 7) * 4;
            float4 w4 = *(const float4*)&W[(size_t)(bn + row) * K + k0 + kq];
            uint32_t h, l;
            bfsplit2(w4.x, w4.y, h, l);
            Wh[row * 20 + (kq >> 1)] = h;  Wl[row * 20 + (kq >> 1)] = l;
            bfsplit2(w4.z, w4.w, h, l);
            Wh[row * 20 + (kq >> 1) + 1] = h;  Wl[row * 20 + (kq >> 1) + 1] = l;
        }
        __syncthreads();
#pragma unroll
        for (int kt = 0; kt < 2; kt++) {
            uint32_t ah[2][4], al[2][4];
#pragma unroll
            for (int mt = 0; mt < 2; mt++) {
                int r0 = (wm + mt * 16 + r) * 20 + kt * 8 + c;
                int r1 = r0 + 8 * 20;
                ah[mt][0] = Ah[r0];     al[mt][0] = Al[r0];
                ah[mt][1] = Ah[r1];     al[mt][1] = Al[r1];
                ah[mt][2] = Ah[r0 + 4]; al[mt][2] = Al[r0 + 4];
                ah[mt][3] = Ah[r1 + 4]; al[mt][3] = Al[r1 + 4];
            }
#pragma unroll
            for (int nt = 0; nt < 4; nt++) {
                int w0 = (wn + nt * 8 + r) * 20 + kt * 8 + c;
                uint32_t bh0 = Wh[w0], bh1 = Wh[w0 + 4];
                uint32_t bl0 = Wl[w0], bl1 = Wl[w0 + 4];
#pragma unroll
                for (int mt = 0; mt < 2; mt++) {
                    mma_bf16(acc[mt][nt], ah[mt][0], ah[mt][1], ah[mt][2], ah[mt][3], bh0, bh1);
                    mma_bf16(acc[mt][nt], al[mt][0], al[mt][1], al[mt][2], al[mt][3], bh0, bh1);
                    mma_bf16(acc[mt][nt], ah[mt][0], ah[mt][1], ah[mt][2], ah[mt][3], bl0, bl1);
                }
            }
        }
        __syncthreads();
    }

    // ---- fused epilogue: bias, per-head l2norm, split, store word layouts ----
    const int col_base = bn + wn;
    const int region = col_base >> 8;             // 0=q, 1=k, 2=v
    const int head = (col_base >> 5) & 7;
    float scale_h = 0.f, qe0[4], qe1[4];
    if (region == 0) {
        scale_h = log1pf(expf(temp[head])) * logf(1024.0f);
#pragma unroll
        for (int nt = 0; nt < 4; nt++) {
            qe0[nt] = qe[head * HD + nt * 8 + 2 * c];
            qe1[nt] = qe[head * HD + nt * 8 + 2 * c + 1];
        }
    }
#pragma unroll
    for (int mt = 0; mt < 2; mt++) {
#pragma unroll
        for (int half = 0; half < 2; half++) {
            int row = bm + wm + mt * 16 + r + half * 8;
            int bq = row >> 10, n = row & 1023;
            float v0[4], v1[4];
#pragma unroll
            for (int nt = 0; nt < 4; nt++) {
                int cg = col_base + nt * 8 + 2 * c;
                v0[nt] = acc[mt][nt][half * 2]     + bias[cg];
                v1[nt] = acc[mt][nt][half * 2 + 1] + bias[cg + 1];
            }
            if (region < 2) {
                float ss = 0.f;
#pragma unroll
                for (int nt = 0; nt < 4; nt++) ss += v0[nt] * v0[nt] + v1[nt] * v1[nt];
                ss += __shfl_xor_sync(0xffffffffu, ss, 1);
                ss += __shfl_xor_sync(0xffffffffu, ss, 2);
                float inv = 1.f / fmaxf(sqrtf(ss), 1e-12f);
                size_t base = ((size_t)(bq * 8 + head) * NN + n) * 16;
#pragma unroll
                for (int nt = 0; nt < 4; nt++) {
                    float a = v0[nt] * inv, bv = v1[nt] * inv;
                    if (region == 0) {
                        a  = (a  + qe0[nt]) * scale_h;
                        bv = (bv + qe1[nt]) * scale_h;
                    }
                    uint32_t hh, ll;
                    bfsplit2(a, bv, hh, ll);
                    size_t w = base + nt * 4 + c;
                    if (region == 0) { g_q2h[w] = hh; g_q2l[w] = ll; }
                    else             { g_kh[w]  = hh; g_kl[w]  = ll; }
                }
            } else {
                size_t bh = (size_t)(bq * 8 + head);
                int np = n >> 1;
                bool evenr = ((r & 1) == 0);
#pragma unroll
                for (int nt = 0; nt < 4; nt++) {
                    float ge = __shfl_xor_sync(0xffffffffu, v0[nt], 4);
                    float go = __shfl_xor_sync(0xffffffffu, v1[nt], 4);
                    int dloc = nt * 8 + 2 * c;
                    float p0, p1; int d;
                    if (evenr) { p0 = v0[nt]; p1 = ge;     d = dloc; }
                    else       { p0 = go;     p1 = v1[nt]; d = dloc + 1; }
                    uint32_t hh, ll;
                    bfsplit2(p0, p1, hh, ll);
                    size_t w = (bh * HD + d) * 512 + np;
                    g_vth[w] = hh; g_vtl[w] = ll;
                }
            }
        }
    }
}

// ---------------- generic bf16 GEMM (proj), inline convert -------------------
__global__ void __launch_bounds__(256) gemm_tc(const float* __restrict__ A,
                                               const float* __restrict__ W,
                                               const float* __restrict__ bias,
                                               float* __restrict__ C,
                                               int M, int N, int K) {
    extern __shared__ uint32_t smg[];
    uint32_t* Ah = smg;
    uint32_t* Al = Ah + 128 * 20;
    uint32_t* Wh = Al + 128 * 20;
    uint32_t* Wl = Wh + 64 * 20;
    const int bm = blockIdx.y * 128, bn = blockIdx.x * 64;
    const int tid = threadIdx.x, lane = tid & 31, warp = tid >> 5;
    const int wm = (warp >> 1) * 32, wn = (warp & 1) * 32;
    const int r = lane >> 2, c = lane & 3;

    float acc[2][4][4];
#pragma unroll
    for (int mt = 0; mt < 2; mt++)
#pragma unroll
        for (int nt = 0; nt < 4; nt++)
#pragma unroll
            for (int q = 0; q < 4; q++) acc[mt][nt][q] = 0.f;

    for (int k0 = 0; k0 < K; k0 += 32) {
#pragma unroll
        for (int i = 0; i < 4; i++) {
            int v = tid + i * 256;
            int row = v >> 3, kq = (v & 7) * 4;
            float4 a4 = *(const float4*)&A[(size_t)(bm + row) * K + k0 + kq];
            uint32_t h, l;
            bfsplit2(a4.x, a4.y, h, l);
            Ah[row * 20 + (kq >> 1)] = h;  Al[row * 20 + (kq >> 1)] = l;
            bfsplit2(a4.z, a4.w, h, l);
            Ah[row * 20 + (kq >> 1) + 1] = h;  Al[row * 20 + (kq >> 1) + 1] = l;
        }
#pragma unroll
        for (int i = 0; i < 2; i++) {
            int v = tid + i * 256;
            int row = v >> 3, kq = (v & 7) * 4;
            float4 w4 = *(const float4*)&W[(size_t)(bn + row) * K + k0 + kq];
            uint32_t h, l;
            bfsplit2(w4.x, w4.y, h, l);
            Wh[row * 20 + (kq >> 1)] = h;  Wl[row * 20 + (kq >> 1)] = l;
            bfsplit2(w4.z, w4.w, h, l);
            Wh[row * 20 + (kq >> 1) + 1] = h;  Wl[row * 20 + (kq >> 1) + 1] = l;
        }
        __syncthreads();
#pragma unroll
        for (int kt = 0; kt < 2; kt++) {
            uint32_t ah[2][4], al[2][4];
#pragma unroll
            for (int mt = 0; mt < 2; mt++) {
                int r0 = (wm + mt * 16 + r) * 20 + kt * 8 + c;
                int r1 = r0 + 8 * 20;
                ah[mt][0] = Ah[r0];     al[mt][0] = Al[r0];
                ah[mt][1] = Ah[r1];     al[mt][1] = Al[r1];
                ah[mt][2] = Ah[r0 + 4]; al[mt][2] = Al[r0 + 4];
                ah[mt][3] = Ah[r1 + 4]; al[mt][3] = Al[r1 + 4];
            }
#pragma unroll
            for (int nt = 0; nt < 4; nt++) {
                int w0 = (wn + nt * 8 + r) * 20 + kt * 8 + c;
                uint32_t bh0 = Wh[w0], bh1 = Wh[w0 + 4];
                uint32_t bl0 = Wl[w0], bl1 = Wl[w0 + 4];
#pragma unroll
                for (int mt = 0; mt < 2; mt++) {
                    mma_bf16(acc[mt][nt], ah[mt][0], ah[mt][1], ah[mt][2], ah[mt][3], bh0, bh1);
                    mma_bf16(acc[mt][nt], al[mt][0], al[mt][1], al[mt][2], al[mt][3], bh0, bh1);
                    mma_bf16(acc[mt][nt], ah[mt][0], ah[mt][1], ah[mt][2], ah[mt][3], bl0, bl1);
                }
            }
        }
        __syncthreads();
    }
#pragma unroll
    for (int mt = 0; mt < 2; mt++) {
        int row0 = bm + wm + mt * 16 + r;
        int row1 = row0 + 8;
#pragma unroll
        for (int nt = 0; nt < 4; nt++) {
            int n = bn + wn + nt * 8 + 2 * c;
            float b0 = bias[n], b1 = bias[n + 1];
            *(float2*)&C[(size_t)row0 * N + n] = make_float2(acc[mt][nt][0] + b0, acc[mt][nt][1] + b1);
            *(float2*)&C[(size_t)row1 * N + n] = make_float2(acc[mt][nt][2] + b0, acc[mt][nt][3] + b1);
        }
    }
}

// ---------------- attention: 256 threads, 128 q-rows, cp.async dbuf ----------
#define ABUF 4864   // words: Kh 1280 | Kl 1280 | Vh 1152 | Vl 1152

__global__ __launch_bounds__(256, 2) void attn_tc(float* __restrict__ out) {
    extern __shared__ uint32_t smw[];

    const int n0 = blockIdx.x * 128;
    const int h  = blockIdx.y;
    const int b  = blockIdx.z;
    const int tid = threadIdx.x, lane = tid & 31, warp = tid >> 5;
    const int r = lane >> 2, c = lane & 3;
    const size_t bh = (size_t)(b * NHEADS + h);

    const uint32_t* kh_g  = g_kh  + bh * NN * 16;
    const uint32_t* kl_g  = g_kl  + bh * NN * 16;
    const uint32_t* vth_g = g_vth + bh * HD * 512;
    const uint32_t* vtl_g = g_vtl + bh * HD * 512;

    auto issue = [&](int kt, int buf) {
        uint32_t s0 = (uint32_t)__cvta_generic_to_shared(smw + buf * ABUF);
#pragma unroll
        for (int i = 0; i < 2; i++) {
            int v = tid + i * 256;
            int plane = v >> 8, rem = v & 255;
            int row = rem >> 2, cq = (rem & 3) * 4;
            const uint32_t* src = (plane ? kl_g : kh_g) + (size_t)(kt * 64 + row) * 16 + cq;
            cp16(s0 + (plane * 1280 + row * 20 + cq) * 4, src);
        }
#pragma unroll
        for (int i = 0; i < 2; i++) {
            int v = tid + i * 256;
            int plane = v >> 8, rem = v & 255;
            int d = rem >> 3, cq = (rem & 7) * 4;
            const uint32_t* src = (plane ? vtl_g : vth_g) + (size_t)d * 512 + kt * 32 + cq;
            cp16(s0 + (2560 + plane * 1152 + d * 36 + cq) * 4, src);
        }
    };

    issue(0, 0);
    asm volatile("cp.async.commit_group;");

    // Q fragments (LDG overlaps with first cp.async)
    const int nr = n0 + warp * 16 + r;
    const uint32_t* qh_g = g_q2h + bh * NN * 16;
    const uint32_t* ql_g = g_q2l + bh * NN * 16;
    uint32_t qh[2][4], ql[2][4];
#pragma unroll
    for (int ks = 0; ks < 2; ks++) {
        qh[ks][0] = qh_g[(size_t)nr * 16 + ks * 8 + c];
        qh[ks][1] = qh_g[(size_t)(nr + 8) * 16 + ks * 8 + c];
        qh[ks][2] = qh_g[(size_t)nr * 16 + ks * 8 + 4 + c];
        qh[ks][3] = qh_g[(size_t)(nr + 8) * 16 + ks * 8 + 4 + c];
        ql[ks][0] = ql_g[(size_t)nr * 16 + ks * 8 + c];
        ql[ks][1] = ql_g[(size_t)(nr + 8) * 16 + ks * 8 + c];
        ql[ks][2] = ql_g[(size_t)nr * 16 + ks * 8 + 4 + c];
        ql[ks][3] = ql_g[(size_t)(nr + 8) * 16 + ks * 8 + 4 + c];
    }

    const uint32_t* b0p = g_bias + ((size_t)h * NN + nr) * 512;
    const uint32_t* b1p = b0p + 8 * 512;

    float O[4][4] = {};
    float ml0 = -1e30f, ml1 = -1e30f, ll0 = 0.f, ll1 = 0.f;

    for (int kt = 0; kt < 16; kt++) {
        __syncthreads();
        if (kt < 15) {
            issue(kt + 1, (kt + 1) & 1);
            asm volatile("cp.async.commit_group;");
            asm volatile("cp.async.wait_group 1;");
        } else {
            asm volatile("cp.async.wait_group 0;");
        }
        __syncthreads();

        const uint32_t* Khb = smw + (kt & 1) * ABUF;
        const uint32_t* Klb = Khb + 1280;
        const uint32_t* Vhb = Khb + 2560;
        const uint32_t* Vlb = Khb + 3712;

        // bias loads issued now, consumed after the MMAs (latency hidden)
        uint32_t bw0[8], bw1[8];
#pragma unroll
        for (int j = 0; j < 8; j++) {
            bw0[j] = b0p[kt * 32 + j * 4 + c];
            bw1[j] = b1p[kt * 32 + j * 4 + c];
        }

        // ---- S = Q K^T (3-plane bf16) ----
        float sc[8][4] = {};
#pragma unroll
        for (int j = 0; j < 8; j++) {
            int rowb = (j * 8 + r) * 20;
#pragma unroll
            for (int ks = 0; ks < 2; ks++) {
                uint32_t bh0 = Khb[rowb + ks * 8 + c], bh1 = Khb[rowb + ks * 8 + 4 + c];
                uint32_t bl0 = Klb[rowb + ks * 8 + c], bl1 = Klb[rowb + ks * 8 + 4 + c];
                mma_bf16(sc[j], qh[ks][0], qh[ks][1], qh[ks][2], qh[ks][3], bh0, bh1);
                mma_bf16(sc[j], ql[ks][0], ql[ks][1], ql[ks][2], ql[ks][3], bh0, bh1);
                mma_bf16(sc[j], qh[ks][0], qh[ks][1], qh[ks][2], qh[ks][3], bl0, bl1);
            }
        }
        // add relative-position bias
#pragma unroll
        for (int j = 0; j < 8; j++) {
            sc[j][0] += __uint_as_float(bw0[j] << 16);
            sc[j][1] += __uint_as_float(bw0[j] & 0xffff0000u);
            sc[j][2] += __uint_as_float(bw1[j] << 16);
            sc[j][3] += __uint_as_float(bw1[j] & 0xffff0000u);
        }

        // ---- online softmax ----
        float mx0 = -1e30f, mx1 = -1e30f;
#pragma unroll
        for (int j = 0; j < 8; j++) {
            mx0 = fmaxf(mx0, fmaxf(sc[j][0], sc[j][1]));
            mx1 = fmaxf(mx1, fmaxf(sc[j][2], sc[j][3]));
        }
        mx0 = fmaxf(mx0, __shfl_xor_sync(0xffffffffu, mx0, 1));
        mx0 = fmaxf(mx0, __shfl_xor_sync(0xffffffffu, mx0, 2));
        mx1 = fmaxf(mx1, __shfl_xor_sync(0xffffffffu, mx1, 1));
        mx1 = fmaxf(mx1, __shfl_xor_sync(0xffffffffu, mx1, 2));
        float mn0 = fmaxf(ml0, mx0), mn1 = fmaxf(ml1, mx1);
        float a0 = __expf(ml0 - mn0), a1 = __expf(ml1 - mn1);
        float s0 = 0.f, s1 = 0.f;
        uint32_t phr[8], phr8[8], plr[8], plr8[8];
#pragma unroll
        for (int j = 0; j < 8; j++) {
            float p0 = __expf(sc[j][0] - mn0), p1 = __expf(sc[j][1] - mn0);
            float p2 = __expf(sc[j][2] - mn1), p3 = __expf(sc[j][3] - mn1);
            s0 += p0 + p1; s1 += p2 + p3;
            bfsplit2(p0, p1, phr[j],  plr[j]);
            bfsplit2(p2, p3, phr8[j], plr8[j]);
        }
        s0 += __shfl_xor_sync(0xffffffffu, s0, 1);
        s0 += __shfl_xor_sync(0xffffffffu, s0, 2);
        s1 += __shfl_xor_sync(0xffffffffu, s1, 1);
        s1 += __shfl_xor_sync(0xffffffffu, s1, 2);
        ll0 = ll0 * a0 + s0; ll1 = ll1 * a1 + s1;
        ml0 = mn0; ml1 = mn1;
#pragma unroll
        for (int jd = 0; jd < 4; jd++) {
            O[jd][0] *= a0; O[jd][1] *= a0;
            O[jd][2] *= a1; O[jd][3] *= a1;
        }

        // ---- O += P @ V (register-chained P, 3-term) ----
#pragma unroll
        for (int kk = 0; kk < 4; kk++) {
            uint32_t a0h = phr[2 * kk],     a1h = phr8[2 * kk];
            uint32_t a2h = phr[2 * kk + 1], a3h = phr8[2 * kk + 1];
            uint32_t a0l = plr[2 * kk],     a1l = plr8[2 * kk];
            uint32_t a2l = plr[2 * kk + 1], a3l = plr8[2 * kk + 1];
#pragma unroll
            for (int jd = 0; jd < 4; jd++) {
                int w0 = (jd * 8 + r) * 36 + kk * 8 + c;
                uint32_t vh0 = Vhb[w0], vh1 = Vhb[w0 + 4];
                uint32_t vl0 = Vlb[w0], vl1 = Vlb[w0 + 4];
                mma_bf16(O[jd], a0h, a1h, a2h, a3h, vh0, vh1);
                mma_bf16(O[jd], a0l, a1l, a2l, a3l, vh0, vh1);
                mma_bf16(O[jd], a0h, a1h, a2h, a3h, vl0, vl1);
            }
        }
    }

    // ---- epilogue: normalize + write f32 [b][n][h*32+d] ----
    float i0 = 1.f / ll0, i1 = 1.f / ll1;
    int row0 = nr;
    int row1 = nr + 8;
#pragma unroll
    for (int jd = 0; jd < 4; jd++) {
        int col = h * HD + jd * 8 + 2 * c;
        *(float2*)&out[(size_t)(b * NN + row0) * CDIM + col] =
            make_float2(O[jd][0] * i0, O[jd][1] * i0);
        *(float2*)&out[(size_t)(b * NN + row1) * CDIM + col] =
            make_float2(O[jd][2] * i1, O[jd][3] * i1);
    }
}

// ---------------- launch ------------------------------------------------------
extern "C" void kernel_launch(void* const* d_in, const int* in_sizes, int n_in,
                              void* d_out, int out_size) {
    int s = (n_in >= 15) ? 0 : -2;
    const float* x       = (const float*)d_in[0];
    const int*   rpi     = (const int*)  d_in[3 + s];
    const float* coords  = (const float*)d_in[4 + s];
    const float* qkv_w   = (const float*)d_in[5 + s];
    const float* qkv_b   = (const float*)d_in[6 + s];
    const float* qe      = (const float*)d_in[7 + s];
    const float* temp    = (const float*)d_in[8 + s];
    const float* proj_w  = (const float*)d_in[9 + s];
    const float* proj_b  = (const float*)d_in[10 + s];
    const float* fc1w    = (const float*)d_in[11 + s];
    const float* fc1b    = (const float*)d_in[12 + s];
    const float* fc2w    = (const float*)d_in[13 + s];
    const float* fc2b    = (const float*)d_in[14 + s];
    float* out = (float*)d_out;

    float* p_ao;
    cudaGetSymbolAddress((void**)&p_ao, g_ao);

    cpb_kernel<<<(TABLE_SZ + 31) / 32, 256>>>(coords, fc1w, fc1b, fc2w, fc2b);
    bias_expand<<<NHEADS * 64, 256>>>(rpi);

    size_t gemm_smem = (2 * 128 * 20 + 2 * 64 * 20) * sizeof(uint32_t);   // 30.7 KB
    cudaFuncSetAttribute(gemm_qkv_fused, cudaFuncAttributeMaxDynamicSharedMemorySize, (int)gemm_smem);
    cudaFuncSetAttribute(gemm_tc, cudaFuncAttributeMaxDynamicSharedMemorySize, (int)gemm_smem);

    gemm_qkv_fused<<<dim3(768 / 64, (BB * NN) / 128), 256, gemm_smem>>>(
        x, qkv_w, qkv_b, qe, temp);

    {
        size_t smem = 2 * ABUF * sizeof(uint32_t);    // 38.9 KB
        cudaFuncSetAttribute(attn_tc, cudaFuncAttributeMaxDynamicSharedMemorySize, (int)smem);
        attn_tc<<<dim3(8, NHEADS, BB), 256, smem>>>(p_ao);
    }

    gemm_tc<<<dim3(CDIM / 64, (BB * NN) / 128), 256, gemm_smem>>>(
        p_ao, proj_w, proj_b, out, BB * NN, CDIM, CDIM);
}

// round 8
// speedup vs baseline: 1.1888x; 1.1464x over previous
#include <cuda_runtime.h>
#include <math.h>
#include <stdint.h>

#define BB      8
#define NHEADS  8
#define HD      32
#define NN      1024
#define CDIM    256
#define TABLE_SZ 3969
#define CPBH    512

// ---------------- scratch (bf16 hi/lo word layouts) -------------------------
__device__ __align__(16) uint32_t g_q2h[BB * NHEADS * NN * 16];
__device__ __align__(16) uint32_t g_q2l[BB * NHEADS * NN * 16];
__device__ __align__(16) uint32_t g_kh [BB * NHEADS * NN * 16];
__device__ __align__(16) uint32_t g_kl [BB * NHEADS * NN * 16];
__device__ __align__(16) uint32_t g_vth[BB * NHEADS * HD * (NN / 2)];
__device__ __align__(16) uint32_t g_vtl[BB * NHEADS * HD * (NN / 2)];
__device__ __align__(16) uint32_t g_bias[NHEADS * NN * (NN / 2)];    // bf16x2
__device__ float g_tab[NHEADS * TABLE_SZ];
__device__ float g_tabmax[NHEADS];
__device__ float g_smax[BB * NHEADS * NN];     // ||qs_n|| per (b,h,n)
__device__ float g_ao [BB * NN * CDIM];

// ---------------- bf16 helpers ----------------------------------------------
__device__ __forceinline__ uint32_t bf16x2(float lo, float hi) {
    uint32_t d;
    asm("cvt.rn.bf16x2.f32 %0, %1, %2;" : "=r"(d) : "f"(hi), "f"(lo));
    return d;
}
__device__ __forceinline__ void bfsplit2(float x0, float x1, uint32_t &hi, uint32_t &lo) {
    uint32_t h = bf16x2(x0, x1);
    float r0 = x0 - __uint_as_float(h << 16);
    float r1 = x1 - __uint_as_float(h & 0xffff0000u);
    hi = h;
    lo = bf16x2(r0, r1);
}
__device__ __forceinline__ void mma_bf16(float c[4],
                                         uint32_t a0, uint32_t a1, uint32_t a2, uint32_t a3,
                                         uint32_t b0, uint32_t b1) {
    asm volatile(
        "mma.sync.aligned.m16n8k16.row.col.f32.bf16.bf16.f32 "
        "{%0,%1,%2,%3}, {%4,%5,%6,%7}, {%8,%9}, {%0,%1,%2,%3};"
        : "+f"(c[0]), "+f"(c[1]), "+f"(c[2]), "+f"(c[3])
        : "r"(a0), "r"(a1), "r"(a2), "r"(a3), "r"(b0), "r"(b1));
}
__device__ __forceinline__ void cp16(uint32_t dst, const void* src) {
    asm volatile("cp.async.cg.shared.global [%0], [%1], 16;" :: "r"(dst), "l"(src));
}

// ---------------- CPB MLP (SMEM-staged weights, warp-per-entry) --------------
__global__ __launch_bounds__(256) void cpb_kernel(const float* __restrict__ coords,
                                                  const float* __restrict__ fc1w,
                                                  const float* __restrict__ fc1b,
                                                  const float* __restrict__ fc2w,
                                                  const float* __restrict__ fc2b) {
    __shared__ float s_w1[CPBH * 2];
    __shared__ float s_b1[CPBH];
    __shared__ float s_w2[NHEADS * CPBH];
    const int tid = threadIdx.x;
    for (int i = tid; i < CPBH * 2; i += 256) s_w1[i] = fc1w[i];
    for (int i = tid; i < CPBH; i += 256) s_b1[i] = fc1b[i];
    for (int i = tid; i < NHEADS * CPBH; i += 256) s_w2[i] = fc2w[i];
    __syncthreads();
    const int warp = tid >> 5, lane = tid & 31;
#pragma unroll
    for (int e = 0; e < 4; e++) {
        int t = blockIdx.x * 32 + warp * 4 + e;
        if (t >= TABLE_SZ) continue;
        float c0 = coords[2 * t], c1 = coords[2 * t + 1];
        float acc[NHEADS];
#pragma unroll
        for (int h = 0; h < NHEADS; h++) acc[h] = 0.f;
#pragma unroll 4
        for (int j = lane; j < CPBH; j += 32) {
            float hv = fmaxf(c0 * s_w1[2 * j] + c1 * s_w1[2 * j + 1] + s_b1[j], 0.f);
#pragma unroll
            for (int h = 0; h < NHEADS; h++) acc[h] += hv * s_w2[h * CPBH + j];
        }
#pragma unroll
        for (int h = 0; h < NHEADS; h++) {
#pragma unroll
            for (int o = 16; o; o >>= 1) acc[h] += __shfl_xor_sync(0xffffffffu, acc[h], o);
            if (lane == 0) g_tab[h * TABLE_SZ + t] = acc[h] + fc2b[h];
        }
    }
}

// ---------------- bias expand + per-head max ----------------------------------
__global__ __launch_bounds__(256) void bias_expand(const int* __restrict__ rpi) {
    __shared__ float tab_s[TABLE_SZ];
    __shared__ float redm[8];
    int h = blockIdx.x >> 6;
    int chunk = blockIdx.x & 63;
    for (int i = threadIdx.x; i < TABLE_SZ; i += 256) tab_s[i] = g_tab[h * TABLE_SZ + i];
    __syncthreads();
    if (chunk == 0) {
        float m = -1e30f;
        for (int i = threadIdx.x; i < TABLE_SZ; i += 256) m = fmaxf(m, tab_s[i]);
#pragma unroll
        for (int o = 16; o; o >>= 1) m = fmaxf(m, __shfl_xor_sync(0xffffffffu, m, o));
        if ((threadIdx.x & 31) == 0) redm[threadIdx.x >> 5] = m;
        __syncthreads();
        if (threadIdx.x == 0) {
            float mm = redm[0];
            for (int w = 1; w < 8; w++) mm = fmaxf(mm, redm[w]);
            g_tabmax[h] = mm;
        }
    }
    for (int i = threadIdx.x; i < 16 * 512; i += 256) {
        int nl = i >> 9, mw = i & 511;
        int n = chunk * 16 + nl;
        int2 id = *(const int2*)&rpi[(size_t)n * NN + 2 * mw];
        g_bias[((size_t)h * NN + n) * 512 + mw] = bf16x2(tab_s[id.x], tab_s[id.y]);
    }
}

// ---------------- fused qkv GEMM + l2norm + split -> word layouts ------------
// 128x64 tile, 256 threads, warps 4x2, BK=32, register-prefetch pipeline.
__global__ __launch_bounds__(256) void gemm_qkv_fused(
        const float* __restrict__ A, const float* __restrict__ W,
        const float* __restrict__ bias,
        const float* __restrict__ qe, const float* __restrict__ temp) {
    extern __shared__ uint32_t smg[];
    uint32_t* Ah = smg;               // [128][20]
    uint32_t* Al = Ah + 128 * 20;
    uint32_t* Wh = Al + 128 * 20;     // [64][20]
    uint32_t* Wl = Wh + 64 * 20;
    const int bm = blockIdx.y * 128, bn = blockIdx.x * 64;
    const int tid = threadIdx.x, lane = tid & 31, warp = tid >> 5;
    const int wm = (warp >> 1) * 32, wn = (warp & 1) * 32;
    const int r = lane >> 2, c = lane & 3;
    const int K = CDIM;

    float acc[2][4][4];
#pragma unroll
    for (int mt = 0; mt < 2; mt++)
#pragma unroll
        for (int nt = 0; nt < 4; nt++)
#pragma unroll
            for (int q = 0; q < 4; q++) acc[mt][nt][q] = 0.f;

    float4 pa[4], pw[2];
#pragma unroll
    for (int i = 0; i < 4; i++) {
        int v = tid + i * 256; int row = v >> 3, kq = (v & 7) * 4;
        pa[i] = *(const float4*)&A[(size_t)(bm + row) * K + kq];
    }
#pragma unroll
    for (int i = 0; i < 2; i++) {
        int v = tid + i * 256; int row = v >> 3, kq = (v & 7) * 4;
        pw[i] = *(const float4*)&W[(size_t)(bn + row) * K + kq];
    }

    for (int k0 = 0; k0 < K; k0 += 32) {
#pragma unroll
        for (int i = 0; i < 4; i++) {
            int v = tid + i * 256; int row = v >> 3, kq = (v & 7) * 4;
            uint32_t h, l;
            bfsplit2(pa[i].x, pa[i].y, h, l);
            Ah[row * 20 + (kq >> 1)] = h;  Al[row * 20 + (kq >> 1)] = l;
            bfsplit2(pa[i].z, pa[i].w, h, l);
            Ah[row * 20 + (kq >> 1) + 1] = h;  Al[row * 20 + (kq >> 1) + 1] = l;
        }
#pragma unroll
        for (int i = 0; i < 2; i++) {
            int v = tid + i * 256; int row = v >> 3, kq = (v & 7) * 4;
            uint32_t h, l;
            bfsplit2(pw[i].x, pw[i].y, h, l);
            Wh[row * 20 + (kq >> 1)] = h;  Wl[row * 20 + (kq >> 1)] = l;
            bfsplit2(pw[i].z, pw[i].w, h, l);
            Wh[row * 20 + (kq >> 1) + 1] = h;  Wl[row * 20 + (kq >> 1) + 1] = l;
        }
        __syncthreads();
        if (k0 + 32 < K) {
#pragma unroll
            for (int i = 0; i < 4; i++) {
                int v = tid + i * 256; int row = v >> 3, kq = (v & 7) * 4;
                pa[i] = *(const float4*)&A[(size_t)(bm + row) * K + k0 + 32 + kq];
            }
#pragma unroll
            for (int i = 0; i < 2; i++) {
                int v = tid + i * 256; int row = v >> 3, kq = (v & 7) * 4;
                pw[i] = *(const float4*)&W[(size_t)(bn + row) * K + k0 + 32 + kq];
            }
        }
#pragma unroll
        for (int kt = 0; kt < 2; kt++) {
            uint32_t ah[2][4], al[2][4];
#pragma unroll
            for (int mt = 0; mt < 2; mt++) {
                int r0 = (wm + mt * 16 + r) * 20 + kt * 8 + c;
                int r1 = r0 + 8 * 20;
                ah[mt][0] = Ah[r0];     al[mt][0] = Al[r0];
                ah[mt][1] = Ah[r1];     al[mt][1] = Al[r1];
                ah[mt][2] = Ah[r0 + 4]; al[mt][2] = Al[r0 + 4];
                ah[mt][3] = Ah[r1 + 4]; al[mt][3] = Al[r1 + 4];
            }
#pragma unroll
            for (int nt = 0; nt < 4; nt++) {
                int w0 = (wn + nt * 8 + r) * 20 + kt * 8 + c;
                uint32_t bh0 = Wh[w0], bh1 = Wh[w0 + 4];
                uint32_t bl0 = Wl[w0], bl1 = Wl[w0 + 4];
#pragma unroll
                for (int mt = 0; mt < 2; mt++) {
                    mma_bf16(acc[mt][nt], ah[mt][0], ah[mt][1], ah[mt][2], ah[mt][3], bh0, bh1);
                    mma_bf16(acc[mt][nt], al[mt][0], al[mt][1], al[mt][2], al[mt][3], bh0, bh1);
                    mma_bf16(acc[mt][nt], ah[mt][0], ah[mt][1], ah[mt][2], ah[mt][3], bl0, bl1);
                }
            }
        }
        __syncthreads();
    }

    // ---- fused epilogue ----
    const int col_base = bn + wn;
    const int region = col_base >> 8;             // 0=q, 1=k, 2=v
    const int head = (col_base >> 5) & 7;
    float scale_h = 0.f, qe0[4], qe1[4];
    if (region == 0) {
        scale_h = log1pf(expf(temp[head])) * logf(1024.0f);
#pragma unroll
        for (int nt = 0; nt < 4; nt++) {
            qe0[nt] = qe[head * HD + nt * 8 + 2 * c];
            qe1[nt] = qe[head * HD + nt * 8 + 2 * c + 1];
        }
    }
#pragma unroll
    for (int mt = 0; mt < 2; mt++) {
#pragma unroll
        for (int half = 0; half < 2; half++) {
            int row = bm + wm + mt * 16 + r + half * 8;
            int bq = row >> 10, n = row & 1023;
            float v0[4], v1[4];
#pragma unroll
            for (int nt = 0; nt < 4; nt++) {
                int cg = col_base + nt * 8 + 2 * c;
                v0[nt] = acc[mt][nt][half * 2]     + bias[cg];
                v1[nt] = acc[mt][nt][half * 2 + 1] + bias[cg + 1];
            }
            if (region < 2) {
                float ss = 0.f;
#pragma unroll
                for (int nt = 0; nt < 4; nt++) ss += v0[nt] * v0[nt] + v1[nt] * v1[nt];
                ss += __shfl_xor_sync(0xffffffffu, ss, 1);
                ss += __shfl_xor_sync(0xffffffffu, ss, 2);
                float inv = 1.f / fmaxf(sqrtf(ss), 1e-12f);
                size_t base = ((size_t)(bq * 8 + head) * NN + n) * 16;
                float ss2 = 0.f;
#pragma unroll
                for (int nt = 0; nt < 4; nt++) {
                    float a = v0[nt] * inv, bv = v1[nt] * inv;
                    if (region == 0) {
                        a  = (a  + qe0[nt]) * scale_h;
                        bv = (bv + qe1[nt]) * scale_h;
                        ss2 += a * a + bv * bv;
                    }
                    uint32_t hh, ll;
                    bfsplit2(a, bv, hh, ll);
                    size_t w = base + nt * 4 + c;
                    if (region == 0) { g_q2h[w] = hh; g_q2l[w] = ll; }
                    else             { g_kh[w]  = hh; g_kl[w]  = ll; }
                }
                if (region == 0) {
                    ss2 += __shfl_xor_sync(0xffffffffu, ss2, 1);
                    ss2 += __shfl_xor_sync(0xffffffffu, ss2, 2);
                    if (c == 0)
                        g_smax[(size_t)(bq * 8 + head) * NN + n] = sqrtf(ss2);
                }
            } else {
                size_t bh = (size_t)(bq * 8 + head);
                int np = n >> 1;
                bool evenr = ((r & 1) == 0);
#pragma unroll
                for (int nt = 0; nt < 4; nt++) {
                    float ge = __shfl_xor_sync(0xffffffffu, v0[nt], 4);
                    float go = __shfl_xor_sync(0xffffffffu, v1[nt], 4);
                    int dloc = nt * 8 + 2 * c;
                    float p0, p1; int d;
                    if (evenr) { p0 = v0[nt]; p1 = ge;     d = dloc; }
                    else       { p0 = go;     p1 = v1[nt]; d = dloc + 1; }
                    uint32_t hh, ll;
                    bfsplit2(p0, p1, hh, ll);
                    size_t w = (bh * HD + d) * 512 + np;
                    g_vth[w] = hh; g_vtl[w] = ll;
                }
            }
        }
    }
}

// ---------------- proj GEMM (inline convert + reg prefetch) ------------------
__global__ void __launch_bounds__(256) gemm_tc(const float* __restrict__ A,
                                               const float* __restrict__ W,
                                               const float* __restrict__ bias,
                                               float* __restrict__ C,
                                               int M, int N, int K) {
    extern __shared__ uint32_t smg[];
    uint32_t* Ah = smg;
    uint32_t* Al = Ah + 128 * 20;
    uint32_t* Wh = Al + 128 * 20;
    uint32_t* Wl = Wh + 64 * 20;
    const int bm = blockIdx.y * 128, bn = blockIdx.x * 64;
    const int tid = threadIdx.x, lane = tid & 31, warp = tid >> 5;
    const int wm = (warp >> 1) * 32, wn = (warp & 1) * 32;
    const int r = lane >> 2, c = lane & 3;

    float acc[2][4][4];
#pragma unroll
    for (int mt = 0; mt < 2; mt++)
#pragma unroll
        for (int nt = 0; nt < 4; nt++)
#pragma unroll
            for (int q = 0; q < 4; q++) acc[mt][nt][q] = 0.f;

    float4 pa[4], pw[2];
#pragma unroll
    for (int i = 0; i < 4; i++) {
        int v = tid + i * 256; int row = v >> 3, kq = (v & 7) * 4;
        pa[i] = *(const float4*)&A[(size_t)(bm + row) * K + kq];
    }
#pragma unroll
    for (int i = 0; i < 2; i++) {
        int v = tid + i * 256; int row = v >> 3, kq = (v & 7) * 4;
        pw[i] = *(const float4*)&W[(size_t)(bn + row) * K + kq];
    }

    for (int k0 = 0; k0 < K; k0 += 32) {
#pragma unroll
        for (int i = 0; i < 4; i++) {
            int v = tid + i * 256; int row = v >> 3, kq = (v & 7) * 4;
            uint32_t h, l;
            bfsplit2(pa[i].x, pa[i].y, h, l);
            Ah[row * 20 + (kq >> 1)] = h;  Al[row * 20 + (kq >> 1)] = l;
            bfsplit2(pa[i].z, pa[i].w, h, l);
            Ah[row * 20 + (kq >> 1) + 1] = h;  Al[row * 20 + (kq >> 1) + 1] = l;
        }
#pragma unroll
        for (int i = 0; i < 2; i++) {
            int v = tid + i * 256; int row = v >> 3, kq = (v & 7) * 4;
            uint32_t h, l;
            bfsplit2(pw[i].x, pw[i].y, h, l);
            Wh[row * 20 + (kq >> 1)] = h;  Wl[row * 20 + (kq >> 1)] = l;
            bfsplit2(pw[i].z, pw[i].w, h, l);
            Wh[row * 20 + (kq >> 1) + 1] = h;  Wl[row * 20 + (kq >> 1) + 1] = l;
        }
        __syncthreads();
        if (k0 + 32 < K) {
#pragma unroll
            for (int i = 0; i < 4; i++) {
                int v = tid + i * 256; int row = v >> 3, kq = (v & 7) * 4;
                pa[i] = *(const float4*)&A[(size_t)(bm + row) * K + k0 + 32 + kq];
            }
#pragma unroll
            for (int i = 0; i < 2; i++) {
                int v = tid + i * 256; int row = v >> 3, kq = (v & 7) * 4;
                pw[i] = *(const float4*)&W[(size_t)(bn + row) * K + k0 + 32 + kq];
            }
        }
#pragma unroll
        for (int kt = 0; kt < 2; kt++) {
            uint32_t ah[2][4], al[2][4];
#pragma unroll
            for (int mt = 0; mt < 2; mt++) {
                int r0 = (wm + mt * 16 + r) * 20 + kt * 8 + c;
                int r1 = r0 + 8 * 20;
                ah[mt][0] = Ah[r0];     al[mt][0] = Al[r0];
                ah[mt][1] = Ah[r1];     al[mt][1] = Al[r1];
                ah[mt][2] = Ah[r0 + 4]; al[mt][2] = Al[r0 + 4];
                ah[mt][3] = Ah[r1 + 4]; al[mt][3] = Al[r1 + 4];
            }
#pragma unroll
            for (int nt = 0; nt < 4; nt++) {
                int w0 = (wn + nt * 8 + r) * 20 + kt * 8 + c;
                uint32_t bh0 = Wh[w0], bh1 = Wh[w0 + 4];
                uint32_t bl0 = Wl[w0], bl1 = Wl[w0 + 4];
#pragma unroll
                for (int mt = 0; mt < 2; mt++) {
                    mma_bf16(acc[mt][nt], ah[mt][0], ah[mt][1], ah[mt][2], ah[mt][3], bh0, bh1);
                    mma_bf16(acc[mt][nt], al[mt][0], al[mt][1], al[mt][2], al[mt][3], bh0, bh1);
                    mma_bf16(acc[mt][nt], ah[mt][0], ah[mt][1], ah[mt][2], ah[mt][3], bl0, bl1);
                }
            }
        }
        __syncthreads();
    }
#pragma unroll
    for (int mt = 0; mt < 2; mt++) {
        int row0 = bm + wm + mt * 16 + r;
        int row1 = row0 + 8;
#pragma unroll
        for (int nt = 0; nt < 4; nt++) {
            int n = bn + wn + nt * 8 + 2 * c;
            float b0 = bias[n], b1 = bias[n + 1];
            *(float2*)&C[(size_t)row0 * N + n] = make_float2(acc[mt][nt][0] + b0, acc[mt][nt][1] + b1);
            *(float2*)&C[(size_t)row1 * N + n] = make_float2(acc[mt][nt][2] + b0, acc[mt][nt][3] + b1);
        }
    }
}

// ---------------- attention: 128 threads, fixed-max softmax ------------------
#define ABUF 4864   // words: Kh 1280 | Kl 1280 | Vh 1152 | Vl 1152

__global__ __launch_bounds__(128, 4) void attn_tc(float* __restrict__ out) {
    extern __shared__ uint32_t smw[];

    const int n0 = blockIdx.x * 64;
    const int h  = blockIdx.y;
    const int b  = blockIdx.z;
    const int tid = threadIdx.x, lane = tid & 31, warp = tid >> 5;
    const int r = lane >> 2, c = lane & 3;
    const size_t bh = (size_t)(b * NHEADS + h);

    const uint32_t* kh_g  = g_kh  + bh * NN * 16;
    const uint32_t* kl_g  = g_kl  + bh * NN * 16;
    const uint32_t* vth_g = g_vth + bh * HD * 512;
    const uint32_t* vtl_g = g_vtl + bh * HD * 512;

    auto issue = [&](int kt, int buf) {
        uint32_t s0 = (uint32_t)__cvta_generic_to_shared(smw + buf * ABUF);
#pragma unroll
        for (int i = 0; i < 4; i++) {
            int v = tid + i * 128;
            int plane = v >> 8, rem = v & 255;
            int row = rem >> 2, cq = (rem & 3) * 4;
            const uint32_t* src = (plane ? kl_g : kh_g) + (size_t)(kt * 64 + row) * 16 + cq;
            cp16(s0 + (plane * 1280 + row * 20 + cq) * 4, src);
        }
#pragma unroll
        for (int i = 0; i < 4; i++) {
            int v = tid + i * 128;
            int plane = v >> 8, rem = v & 255;
            int d = rem >> 3, cq = (rem & 7) * 4;
            const uint32_t* src = (plane ? vtl_g : vth_g) + (size_t)d * 512 + kt * 32 + cq;
            cp16(s0 + (2560 + plane * 1152 + d * 36 + cq) * 4, src);
        }
    };

    issue(0, 0);
    asm volatile("cp.async.commit_group;");

    // Q fragments + softmax shift constants (LDG overlaps first cp.async)
    const int nr = n0 + warp * 16 + r;
    const uint32_t* qh_g = g_q2h + bh * NN * 16;
    const uint32_t* ql_g = g_q2l + bh * NN * 16;
    uint32_t qh[2][4], ql[2][4];
#pragma unroll
    for (int ks = 0; ks < 2; ks++) {
        qh[ks][0] = qh_g[(size_t)nr * 16 + ks * 8 + c];
        qh[ks][1] = qh_g[(size_t)(nr + 8) * 16 + ks * 8 + c];
        qh[ks][2] = qh_g[(size_t)nr * 16 + ks * 8 + 4 + c];
        qh[ks][3] = qh_g[(size_t)(nr + 8) * 16 + ks * 8 + 4 + c];
        ql[ks][0] = ql_g[(size_t)nr * 16 + ks * 8 + c];
        ql[ks][1] = ql_g[(size_t)(nr + 8) * 16 + ks * 8 + c];
        ql[ks][2] = ql_g[(size_t)nr * 16 + ks * 8 + 4 + c];
        ql[ks][3] = ql_g[(size_t)(nr + 8) * 16 + ks * 8 + 4 + c];
    }
    const float tm = g_tabmax[h];
    const float C0 = g_smax[bh * NN + nr] + tm;
    const float C1 = g_smax[bh * NN + nr + 8] + tm;

    const uint32_t* b0p = g_bias + ((size_t)h * NN + nr) * 512;
    const uint32_t* b1p = b0p + 8 * 512;

    float O[4][4] = {};
    float ll0 = 0.f, ll1 = 0.f;   // per-lane partial sums; reduced at the end

    for (int kt = 0; kt < 16; kt++) {
        __syncthreads();
        if (kt < 15) {
            issue(kt + 1, (kt + 1) & 1);
            asm volatile("cp.async.commit_group;");
            asm volatile("cp.async.wait_group 1;");
        } else {
            asm volatile("cp.async.wait_group 0;");
        }
        __syncthreads();

        const uint32_t* Khb = smw + (kt & 1) * ABUF;
        const uint32_t* Klb = Khb + 1280;
        const uint32_t* Vhb = Khb + 2560;
        const uint32_t* Vlb = Khb + 3712;

        // bias loads issued now, consumed after the MMAs
        uint32_t bw0[8], bw1[8];
#pragma unroll
        for (int j = 0; j < 8; j++) {
            bw0[j] = b0p[kt * 32 + j * 4 + c];
            bw1[j] = b1p[kt * 32 + j * 4 + c];
        }

        // ---- S = Q K^T (3-plane bf16) ----
        float sc[8][4] = {};
#pragma unroll
        for (int j = 0; j < 8; j++) {
            int rowb = (j * 8 + r) * 20;
#pragma unroll
            for (int ks = 0; ks < 2; ks++) {
                uint32_t bh0 = Khb[rowb + ks * 8 + c], bh1 = Khb[rowb + ks * 8 + 4 + c];
                uint32_t bl0 = Klb[rowb + ks * 8 + c], bl1 = Klb[rowb + ks * 8 + 4 + c];
                mma_bf16(sc[j], qh[ks][0], qh[ks][1], qh[ks][2], qh[ks][3], bh0, bh1);
                mma_bf16(sc[j], ql[ks][0], ql[ks][1], ql[ks][2], ql[ks][3], bh0, bh1);
                mma_bf16(sc[j], qh[ks][0], qh[ks][1], qh[ks][2], qh[ks][3], bl0, bl1);
            }
        }

        // ---- fixed-max softmax: p = exp(S + bias - C); no reductions ----
        float s0 = 0.f, s1 = 0.f;
        uint32_t phr[8], phr8[8], plr[8], plr8[8];
#pragma unroll
        for (int j = 0; j < 8; j++) {
            float p0 = __expf(sc[j][0] + __uint_as_float(bw0[j] << 16)          - C0);
            float p1 = __expf(sc[j][1] + __uint_as_float(bw0[j] & 0xffff0000u)  - C0);
            float p2 = __expf(sc[j][2] + __uint_as_float(bw1[j] << 16)          - C1);
            float p3 = __expf(sc[j][3] + __uint_as_float(bw1[j] & 0xffff0000u)  - C1);
            s0 += p0 + p1; s1 += p2 + p3;
            bfsplit2(p0, p1, phr[j],  plr[j]);
            bfsplit2(p2, p3, phr8[j], plr8[j]);
        }
        ll0 += s0; ll1 += s1;

        // ---- O += P @ V (register-chained P, 3-term) ----
#pragma unroll
        for (int kk = 0; kk < 4; kk++) {
            uint32_t a0h = phr[2 * kk],     a1h = phr8[2 * kk];
            uint32_t a2h = phr[2 * kk + 1], a3h = phr8[2 * kk + 1];
            uint32_t a0l = plr[2 * kk],     a1l = plr8[2 * kk];
            uint32_t a2l = plr[2 * kk + 1], a3l = plr8[2 * kk + 1];
#pragma unroll
            for (int jd = 0; jd < 4; jd++) {
                int w0 = (jd * 8 + r) * 36 + kk * 8 + c;
                uint32_t vh0 = Vhb[w0], vh1 = Vhb[w0 + 4];
                uint32_t vl0 = Vlb[w0], vl1 = Vlb[w0 + 4];
                mma_bf16(O[jd], a0h, a1h, a2h, a3h, vh0, vh1);
                mma_bf16(O[jd], a0l, a1l, a2l, a3l, vh0, vh1);
                mma_bf16(O[jd], a0h, a1h, a2h, a3h, vl0, vl1);
            }
        }
    }

    // ---- epilogue: one l-reduction, normalize, write ----
    ll0 += __shfl_xor_sync(0xffffffffu, ll0, 1);
    ll0 += __shfl_xor_sync(0xffffffffu, ll0, 2);
    ll1 += __shfl_xor_sync(0xffffffffu, ll1, 1);
    ll1 += __shfl_xor_sync(0xffffffffu, ll1, 2);
    float i0 = 1.f / ll0, i1 = 1.f / ll1;
#pragma unroll
    for (int jd = 0; jd < 4; jd++) {
        int col = h * HD + jd * 8 + 2 * c;
        *(float2*)&out[(size_t)(b * NN + nr) * CDIM + col] =
            make_float2(O[jd][0] * i0, O[jd][1] * i0);
        *(float2*)&out[(size_t)(b * NN + nr + 8) * CDIM + col] =
            make_float2(O[jd][2] * i1, O[jd][3] * i1);
    }
}

// ---------------- launch ------------------------------------------------------
extern "C" void kernel_launch(void* const* d_in, const int* in_sizes, int n_in,
                              void* d_out, int out_size) {
    int s = (n_in >= 15) ? 0 : -2;
    const float* x       = (const float*)d_in[0];
    const int*   rpi     = (const int*)  d_in[3 + s];
    const float* coords  = (const float*)d_in[4 + s];
    const float* qkv_w   = (const float*)d_in[5 + s];
    const float* qkv_b   = (const float*)d_in[6 + s];
    const float* qe      = (const float*)d_in[7 + s];
    const float* temp    = (const float*)d_in[8 + s];
    const float* proj_w  = (const float*)d_in[9 + s];
    const float* proj_b  = (const float*)d_in[10 + s];
    const float* fc1w    = (const float*)d_in[11 + s];
    const float* fc1b    = (const float*)d_in[12 + s];
    const float* fc2w    = (const float*)d_in[13 + s];
    const float* fc2b    = (const float*)d_in[14 + s];
    float* out = (float*)d_out;

    float* p_ao;
    cudaGetSymbolAddress((void**)&p_ao, g_ao);

    cpb_kernel<<<(TABLE_SZ + 31) / 32, 256>>>(coords, fc1w, fc1b, fc2w, fc2b);
    bias_expand<<<NHEADS * 64, 256>>>(rpi);

    size_t gemm_smem = (2 * 128 * 20 + 2 * 64 * 20) * sizeof(uint32_t);   // 30.7 KB
    cudaFuncSetAttribute(gemm_qkv_fused, cudaFuncAttributeMaxDynamicSharedMemorySize, (int)gemm_smem);
    cudaFuncSetAttribute(gemm_tc, cudaFuncAttributeMaxDynamicSharedMemorySize, (int)gemm_smem);

    gemm_qkv_fused<<<dim3(768 / 64, (BB * NN) / 128), 256, gemm_smem>>>(
        x, qkv_w, qkv_b, qe, temp);

    {
        size_t smem = 2 * ABUF * sizeof(uint32_t);    // 38.9 KB
        cudaFuncSetAttribute(attn_tc, cudaFuncAttributeMaxDynamicSharedMemorySize, (int)smem);
        attn_tc<<<dim3(16, NHEADS, BB), 128, smem>>>(p_ao);
    }

    gemm_tc<<<dim3(CDIM / 64, (BB * NN) / 128), 256, gemm_smem>>>(
        p_ao, proj_w, proj_b, out, BB * NN, CDIM, CDIM);
}

// round 9
// speedup vs baseline: 1.1993x; 1.0088x over previous
#include <cuda_runtime.h>
#include <math.h>
#include <stdint.h>

#define BB      8
#define NHEADS  8
#define HD      32
#define NN      1024
#define CDIM    256
#define TABLE_SZ 3969
#define CPBH    512

// ---------------- scratch (bf16 hi/lo word layouts) -------------------------
__device__ __align__(16) uint32_t g_q2h[BB * NHEADS * NN * 16];
__device__ __align__(16) uint32_t g_q2l[BB * NHEADS * NN * 16];
__device__ __align__(16) uint32_t g_kh [BB * NHEADS * NN * 16];
__device__ __align__(16) uint32_t g_kl [BB * NHEADS * NN * 16];
__device__ __align__(16) uint32_t g_vth[BB * NHEADS * HD * (NN / 2)];
__device__ __align__(16) uint32_t g_vtl[BB * NHEADS * HD * (NN / 2)];
__device__ __align__(16) uint32_t g_bias[NHEADS * NN * (NN / 2)];    // bf16x2
__device__ float g_tab[NHEADS * TABLE_SZ];
__device__ float g_tabmax[NHEADS];
__device__ float g_smax[BB * NHEADS * NN];     // ||qs_n|| per (b,h,n)
__device__ float g_ao [BB * NN * CDIM];

// ---------------- bf16 helpers ----------------------------------------------
__device__ __forceinline__ uint32_t bf16x2(float lo, float hi) {
    uint32_t d;
    asm("cvt.rn.bf16x2.f32 %0, %1, %2;" : "=r"(d) : "f"(hi), "f"(lo));
    return d;
}
__device__ __forceinline__ void bfsplit2(float x0, float x1, uint32_t &hi, uint32_t &lo) {
    uint32_t h = bf16x2(x0, x1);
    float r0 = x0 - __uint_as_float(h << 16);
    float r1 = x1 - __uint_as_float(h & 0xffff0000u);
    hi = h;
    lo = bf16x2(r0, r1);
}
__device__ __forceinline__ void mma_bf16(float c[4],
                                         uint32_t a0, uint32_t a1, uint32_t a2, uint32_t a3,
                                         uint32_t b0, uint32_t b1) {
    asm volatile(
        "mma.sync.aligned.m16n8k16.row.col.f32.bf16.bf16.f32 "
        "{%0,%1,%2,%3}, {%4,%5,%6,%7}, {%8,%9}, {%0,%1,%2,%3};"
        : "+f"(c[0]), "+f"(c[1]), "+f"(c[2]), "+f"(c[3])
        : "r"(a0), "r"(a1), "r"(a2), "r"(a3), "r"(b0), "r"(b1));
}
__device__ __forceinline__ void cp16(uint32_t dst, const void* src) {
    asm volatile("cp.async.cg.shared.global [%0], [%1], 16;" :: "r"(dst), "l"(src));
}

// ---------------- CPB MLP (SMEM-staged weights, warp-per-entry) --------------
__global__ __launch_bounds__(256) void cpb_kernel(const float* __restrict__ coords,
                                                  const float* __restrict__ fc1w,
                                                  const float* __restrict__ fc1b,
                                                  const float* __restrict__ fc2w,
                                                  const float* __restrict__ fc2b) {
    __shared__ float s_w1[CPBH * 2];
    __shared__ float s_b1[CPBH];
    __shared__ float s_w2[NHEADS * CPBH];
    const int tid = threadIdx.x;
    for (int i = tid; i < CPBH * 2; i += 256) s_w1[i] = fc1w[i];
    for (int i = tid; i < CPBH; i += 256) s_b1[i] = fc1b[i];
    for (int i = tid; i < NHEADS * CPBH; i += 256) s_w2[i] = fc2w[i];
    __syncthreads();
    const int warp = tid >> 5, lane = tid & 31;
#pragma unroll
    for (int e = 0; e < 4; e++) {
        int t = blockIdx.x * 32 + warp * 4 + e;
        if (t >= TABLE_SZ) continue;
        float c0 = coords[2 * t], c1 = coords[2 * t + 1];
        float acc[NHEADS];
#pragma unroll
        for (int h = 0; h < NHEADS; h++) acc[h] = 0.f;
#pragma unroll 4
        for (int j = lane; j < CPBH; j += 32) {
            float hv = fmaxf(c0 * s_w1[2 * j] + c1 * s_w1[2 * j + 1] + s_b1[j], 0.f);
#pragma unroll
            for (int h = 0; h < NHEADS; h++) acc[h] += hv * s_w2[h * CPBH + j];
        }
#pragma unroll
        for (int h = 0; h < NHEADS; h++) {
#pragma unroll
            for (int o = 16; o; o >>= 1) acc[h] += __shfl_xor_sync(0xffffffffu, acc[h], o);
            if (lane == 0) g_tab[h * TABLE_SZ + t] = acc[h] + fc2b[h];
        }
    }
}

// ---------------- bias expand + per-head max ----------------------------------
__global__ __launch_bounds__(256) void bias_expand(const int* __restrict__ rpi) {
    __shared__ float tab_s[TABLE_SZ];
    __shared__ float redm[8];
    int h = blockIdx.x >> 6;
    int chunk = blockIdx.x & 63;
    for (int i = threadIdx.x; i < TABLE_SZ; i += 256) tab_s[i] = g_tab[h * TABLE_SZ + i];
    __syncthreads();
    if (chunk == 0) {
        float m = -1e30f;
        for (int i = threadIdx.x; i < TABLE_SZ; i += 256) m = fmaxf(m, tab_s[i]);
#pragma unroll
        for (int o = 16; o; o >>= 1) m = fmaxf(m, __shfl_xor_sync(0xffffffffu, m, o));
        if ((threadIdx.x & 31) == 0) redm[threadIdx.x >> 5] = m;
        __syncthreads();
        if (threadIdx.x == 0) {
            float mm = redm[0];
            for (int w = 1; w < 8; w++) mm = fmaxf(mm, redm[w]);
            g_tabmax[h] = mm;
        }
    }
    for (int i = threadIdx.x; i < 16 * 512; i += 256) {
        int nl = i >> 9, mw = i & 511;
        int n = chunk * 16 + nl;
        int2 id = *(const int2*)&rpi[(size_t)n * NN + 2 * mw];
        g_bias[((size_t)h * NN + n) * 512 + mw] = bf16x2(tab_s[id.x], tab_s[id.y]);
    }
}

// ---------------- fused qkv GEMM + l2norm + split -> word layouts ------------
__global__ __launch_bounds__(256) void gemm_qkv_fused(
        const float* __restrict__ A, const float* __restrict__ W,
        const float* __restrict__ bias,
        const float* __restrict__ qe, const float* __restrict__ temp) {
    extern __shared__ uint32_t smg[];
    uint32_t* Ah = smg;               // [128][20]
    uint32_t* Al = Ah + 128 * 20;
    uint32_t* Wh = Al + 128 * 20;     // [64][20]
    uint32_t* Wl = Wh + 64 * 20;
    const int bm = blockIdx.y * 128, bn = blockIdx.x * 64;
    const int tid = threadIdx.x, lane = tid & 31, warp = tid >> 5;
    const int wm = (warp >> 1) * 32, wn = (warp & 1) * 32;
    const int r = lane >> 2, c = lane & 3;
    const int K = CDIM;

    float acc[2][4][4];
#pragma unroll
    for (int mt = 0; mt < 2; mt++)
#pragma unroll
        for (int nt = 0; nt < 4; nt++)
#pragma unroll
            for (int q = 0; q < 4; q++) acc[mt][nt][q] = 0.f;

    float4 pa[4], pw[2];
#pragma unroll
    for (int i = 0; i < 4; i++) {
        int v = tid + i * 256; int row = v >> 3, kq = (v & 7) * 4;
        pa[i] = *(const float4*)&A[(size_t)(bm + row) * K + kq];
    }
#pragma unroll
    for (int i = 0; i < 2; i++) {
        int v = tid + i * 256; int row = v >> 3, kq = (v & 7) * 4;
        pw[i] = *(const float4*)&W[(size_t)(bn + row) * K + kq];
    }

    for (int k0 = 0; k0 < K; k0 += 32) {
#pragma unroll
        for (int i = 0; i < 4; i++) {
            int v = tid + i * 256; int row = v >> 3, kq = (v & 7) * 4;
            uint32_t h, l;
            bfsplit2(pa[i].x, pa[i].y, h, l);
            Ah[row * 20 + (kq >> 1)] = h;  Al[row * 20 + (kq >> 1)] = l;
            bfsplit2(pa[i].z, pa[i].w, h, l);
            Ah[row * 20 + (kq >> 1) + 1] = h;  Al[row * 20 + (kq >> 1) + 1] = l;
        }
#pragma unroll
        for (int i = 0; i < 2; i++) {
            int v = tid + i * 256; int row = v >> 3, kq = (v & 7) * 4;
            uint32_t h, l;
            bfsplit2(pw[i].x, pw[i].y, h, l);
            Wh[row * 20 + (kq >> 1)] = h;  Wl[row * 20 + (kq >> 1)] = l;
            bfsplit2(pw[i].z, pw[i].w, h, l);
            Wh[row * 20 + (kq >> 1) + 1] = h;  Wl[row * 20 + (kq >> 1) + 1] = l;
        }
        __syncthreads();
        if (k0 + 32 < K) {
#pragma unroll
            for (int i = 0; i < 4; i++) {
                int v = tid + i * 256; int row = v >> 3, kq = (v & 7) * 4;
                pa[i] = *(const float4*)&A[(size_t)(bm + row) * K + k0 + 32 + kq];
            }
#pragma unroll
            for (int i = 0; i < 2; i++) {
                int v = tid + i * 256; int row = v >> 3, kq = (v & 7) * 4;
                pw[i] = *(const float4*)&W[(size_t)(bn + row) * K + k0 + 32 + kq];
            }
        }
#pragma unroll
        for (int kt = 0; kt < 2; kt++) {
            uint32_t ah[2][4], al[2][4];
#pragma unroll
            for (int mt = 0; mt < 2; mt++) {
                int r0 = (wm + mt * 16 + r) * 20 + kt * 8 + c;
                int r1 = r0 + 8 * 20;
                ah[mt][0] = Ah[r0];     al[mt][0] = Al[r0];
                ah[mt][1] = Ah[r1];     al[mt][1] = Al[r1];
                ah[mt][2] = Ah[r0 + 4]; al[mt][2] = Al[r0 + 4];
                ah[mt][3] = Ah[r1 + 4]; al[mt][3] = Al[r1 + 4];
            }
#pragma unroll
            for (int nt = 0; nt < 4; nt++) {
                int w0 = (wn + nt * 8 + r) * 20 + kt * 8 + c;
                uint32_t bh0 = Wh[w0], bh1 = Wh[w0 + 4];
                uint32_t bl0 = Wl[w0], bl1 = Wl[w0 + 4];
#pragma unroll
                for (int mt = 0; mt < 2; mt++) {
                    mma_bf16(acc[mt][nt], ah[mt][0], ah[mt][1], ah[mt][2], ah[mt][3], bh0, bh1);
                    mma_bf16(acc[mt][nt], al[mt][0], al[mt][1], al[mt][2], al[mt][3], bh0, bh1);
                    mma_bf16(acc[mt][nt], ah[mt][0], ah[mt][1], ah[mt][2], ah[mt][3], bl0, bl1);
                }
            }
        }
        __syncthreads();
    }

    // ---- fused epilogue ----
    const int col_base = bn + wn;
    const int region = col_base >> 8;             // 0=q, 1=k, 2=v
    const int head = (col_base >> 5) & 7;
    float scale_h = 0.f, qe0[4], qe1[4];
    if (region == 0) {
        scale_h = log1pf(expf(temp[head])) * logf(1024.0f);
#pragma unroll
        for (int nt = 0; nt < 4; nt++) {
            qe0[nt] = qe[head * HD + nt * 8 + 2 * c];
            qe1[nt] = qe[head * HD + nt * 8 + 2 * c + 1];
        }
    }
#pragma unroll
    for (int mt = 0; mt < 2; mt++) {
#pragma unroll
        for (int half = 0; half < 2; half++) {
            int row = bm + wm + mt * 16 + r + half * 8;
            int bq = row >> 10, n = row & 1023;
            float v0[4], v1[4];
#pragma unroll
            for (int nt = 0; nt < 4; nt++) {
                int cg = col_base + nt * 8 + 2 * c;
                v0[nt] = acc[mt][nt][half * 2]     + bias[cg];
                v1[nt] = acc[mt][nt][half * 2 + 1] + bias[cg + 1];
            }
            if (region < 2) {
                float ss = 0.f;
#pragma unroll
                for (int nt = 0; nt < 4; nt++) ss += v0[nt] * v0[nt] + v1[nt] * v1[nt];
                ss += __shfl_xor_sync(0xffffffffu, ss, 1);
                ss += __shfl_xor_sync(0xffffffffu, ss, 2);
                float inv = 1.f / fmaxf(sqrtf(ss), 1e-12f);
                size_t base = ((size_t)(bq * 8 + head) * NN + n) * 16;
                float ss2 = 0.f;
#pragma unroll
                for (int nt = 0; nt < 4; nt++) {
                    float a = v0[nt] * inv, bv = v1[nt] * inv;
                    if (region == 0) {
                        a  = (a  + qe0[nt]) * scale_h;
                        bv = (bv + qe1[nt]) * scale_h;
                        ss2 += a * a + bv * bv;
                    }
                    uint32_t hh, ll;
                    bfsplit2(a, bv, hh, ll);
                    size_t w = base + nt * 4 + c;
                    if (region == 0) { g_q2h[w] = hh; g_q2l[w] = ll; }
                    else             { g_kh[w]  = hh; g_kl[w]  = ll; }
                }
                if (region == 0) {
                    ss2 += __shfl_xor_sync(0xffffffffu, ss2, 1);
                    ss2 += __shfl_xor_sync(0xffffffffu, ss2, 2);
                    if (c == 0)
                        g_smax[(size_t)(bq * 8 + head) * NN + n] = sqrtf(ss2);
                }
            } else {
                size_t bh = (size_t)(bq * 8 + head);
                int np = n >> 1;
                bool evenr = ((r & 1) == 0);
#pragma unroll
                for (int nt = 0; nt < 4; nt++) {
                    float ge = __shfl_xor_sync(0xffffffffu, v0[nt], 4);
                    float go = __shfl_xor_sync(0xffffffffu, v1[nt], 4);
                    int dloc = nt * 8 + 2 * c;
                    float p0, p1; int d;
                    if (evenr) { p0 = v0[nt]; p1 = ge;     d = dloc; }
                    else       { p0 = go;     p1 = v1[nt]; d = dloc + 1; }
                    uint32_t hh, ll;
                    bfsplit2(p0, p1, hh, ll);
                    size_t w = (bh * HD + d) * 512 + np;
                    g_vth[w] = hh; g_vtl[w] = ll;
                }
            }
        }
    }
}

// ---------------- proj GEMM (inline convert + reg prefetch) ------------------
__global__ void __launch_bounds__(256) gemm_tc(const float* __restrict__ A,
                                               const float* __restrict__ W,
                                               const float* __restrict__ bias,
                                               float* __restrict__ C,
                                               int M, int N, int K) {
    extern __shared__ uint32_t smg[];
    uint32_t* Ah = smg;
    uint32_t* Al = Ah + 128 * 20;
    uint32_t* Wh = Al + 128 * 20;
    uint32_t* Wl = Wh + 64 * 20;
    const int bm = blockIdx.y * 128, bn = blockIdx.x * 64;
    const int tid = threadIdx.x, lane = tid & 31, warp = tid >> 5;
    const int wm = (warp >> 1) * 32, wn = (warp & 1) * 32;
    const int r = lane >> 2, c = lane & 3;

    float acc[2][4][4];
#pragma unroll
    for (int mt = 0; mt < 2; mt++)
#pragma unroll
        for (int nt = 0; nt < 4; nt++)
#pragma unroll
            for (int q = 0; q < 4; q++) acc[mt][nt][q] = 0.f;

    float4 pa[4], pw[2];
#pragma unroll
    for (int i = 0; i < 4; i++) {
        int v = tid + i * 256; int row = v >> 3, kq = (v & 7) * 4;
        pa[i] = *(const float4*)&A[(size_t)(bm + row) * K + kq];
    }
#pragma unroll
    for (int i = 0; i < 2; i++) {
        int v = tid + i * 256; int row = v >> 3, kq = (v & 7) * 4;
        pw[i] = *(const float4*)&W[(size_t)(bn + row) * K + kq];
    }

    for (int k0 = 0; k0 < K; k0 += 32) {
#pragma unroll
        for (int i = 0; i < 4; i++) {
            int v = tid + i * 256; int row = v >> 3, kq = (v & 7) * 4;
            uint32_t h, l;
            bfsplit2(pa[i].x, pa[i].y, h, l);
            Ah[row * 20 + (kq >> 1)] = h;  Al[row * 20 + (kq >> 1)] = l;
            bfsplit2(pa[i].z, pa[i].w, h, l);
            Ah[row * 20 + (kq >> 1) + 1] = h;  Al[row * 20 + (kq >> 1) + 1] = l;
        }
#pragma unroll
        for (int i = 0; i < 2; i++) {
            int v = tid + i * 256; int row = v >> 3, kq = (v & 7) * 4;
            uint32_t h, l;
            bfsplit2(pw[i].x, pw[i].y, h, l);
            Wh[row * 20 + (kq >> 1)] = h;  Wl[row * 20 + (kq >> 1)] = l;
            bfsplit2(pw[i].z, pw[i].w, h, l);
            Wh[row * 20 + (kq >> 1) + 1] = h;  Wl[row * 20 + (kq >> 1) + 1] = l;
        }
        __syncthreads();
        if (k0 + 32 < K) {
#pragma unroll
            for (int i = 0; i < 4; i++) {
                int v = tid + i * 256; int row = v >> 3, kq = (v & 7) * 4;
                pa[i] = *(const float4*)&A[(size_t)(bm + row) * K + k0 + 32 + kq];
            }
#pragma unroll
            for (int i = 0; i < 2; i++) {
                int v = tid + i * 256; int row = v >> 3, kq = (v & 7) * 4;
                pw[i] = *(const float4*)&W[(size_t)(bn + row) * K + k0 + 32 + kq];
            }
        }
#pragma unroll
        for (int kt = 0; kt < 2; kt++) {
            uint32_t ah[2][4], al[2][4];
#pragma unroll
            for (int mt = 0; mt < 2; mt++) {
                int r0 = (wm + mt * 16 + r) * 20 + kt * 8 + c;
                int r1 = r0 + 8 * 20;
                ah[mt][0] = Ah[r0];     al[mt][0] = Al[r0];
                ah[mt][1] = Ah[r1];     al[mt][1] = Al[r1];
                ah[mt][2] = Ah[r0 + 4]; al[mt][2] = Al[r0 + 4];
                ah[mt][3] = Ah[r1 + 4]; al[mt][3] = Al[r1 + 4];
            }
#pragma unroll
            for (int nt = 0; nt < 4; nt++) {
                int w0 = (wn + nt * 8 + r) * 20 + kt * 8 + c;
                uint32_t bh0 = Wh[w0], bh1 = Wh[w0 + 4];
                uint32_t bl0 = Wl[w0], bl1 = Wl[w0 + 4];
#pragma unroll
                for (int mt = 0; mt < 2; mt++) {
                    mma_bf16(acc[mt][nt], ah[mt][0], ah[mt][1], ah[mt][2], ah[mt][3], bh0, bh1);
                    mma_bf16(acc[mt][nt], al[mt][0], al[mt][1], al[mt][2], al[mt][3], bh0, bh1);
                    mma_bf16(acc[mt][nt], ah[mt][0], ah[mt][1], ah[mt][2], ah[mt][3], bl0, bl1);
                }
            }
        }
        __syncthreads();
    }
#pragma unroll
    for (int mt = 0; mt < 2; mt++) {
        int row0 = bm + wm + mt * 16 + r;
        int row1 = row0 + 8;
#pragma unroll
        for (int nt = 0; nt < 4; nt++) {
            int n = bn + wn + nt * 8 + 2 * c;
            float b0 = bias[n], b1 = bias[n + 1];
            *(float2*)&C[(size_t)row0 * N + n] = make_float2(acc[mt][nt][0] + b0, acc[mt][nt][1] + b1);
            *(float2*)&C[(size_t)row1 * N + n] = make_float2(acc[mt][nt][2] + b0, acc[mt][nt][3] + b1);
        }
    }
}

// ---------------- attention: 2x2 (query,key) warp split ----------------------
// 128 threads: warp = qg*2+kg; qg owns 32 q-rows, kg owns 32 of 64 keys/tile.
// Fixed-max softmax -> no cross-key coupling; kg halves merge once at the end.
#define ABUF 4864   // words: Kh 1280 | Kl 1280 | Vh 1152 | Vl 1152

__global__ __launch_bounds__(128, 4) void attn_tc(float* __restrict__ out) {
    extern __shared__ uint32_t smw[];

    const int n0 = blockIdx.x * 64;
    const int h  = blockIdx.y;
    const int b  = blockIdx.z;
    const int tid = threadIdx.x, lane = tid & 31, warp = tid >> 5;
    const int qg = warp >> 1, kg = warp & 1;
    const int r = lane >> 2, c = lane & 3;
    const size_t bh = (size_t)(b * NHEADS + h);

    const uint32_t* kh_g  = g_kh  + bh * NN * 16;
    const uint32_t* kl_g  = g_kl  + bh * NN * 16;
    const uint32_t* vth_g = g_vth + bh * HD * 512;
    const uint32_t* vtl_g = g_vtl + bh * HD * 512;

    auto issue = [&](int kt, int buf) {
        uint32_t s0 = (uint32_t)__cvta_generic_to_shared(smw + buf * ABUF);
#pragma unroll
        for (int i = 0; i < 4; i++) {
            int v = tid + i * 128;
            int plane = v >> 8, rem = v & 255;
            int row = rem >> 2, cq = (rem & 3) * 4;
            const uint32_t* src = (plane ? kl_g : kh_g) + (size_t)(kt * 64 + row) * 16 + cq;
            cp16(s0 + (plane * 1280 + row * 20 + cq) * 4, src);
        }
#pragma unroll
        for (int i = 0; i < 4; i++) {
            int v = tid + i * 128;
            int plane = v >> 8, rem = v & 255;
            int d = rem >> 3, cq = (rem & 7) * 4;
            const uint32_t* src = (plane ? vtl_g : vth_g) + (size_t)d * 512 + kt * 32 + cq;
            cp16(s0 + (2560 + plane * 1152 + d * 36 + cq) * 4, src);
        }
    };

    issue(0, 0);
    asm volatile("cp.async.commit_group;");

    // Q fragments: rows n0 + qg*32 + mt*16 + {r, r+8}
    const uint32_t* qh_g = g_q2h + bh * NN * 16;
    const uint32_t* ql_g = g_q2l + bh * NN * 16;
    uint32_t qh[2][2][4], ql[2][2][4];
#pragma unroll
    for (int mt = 0; mt < 2; mt++) {
        int nr0 = n0 + qg * 32 + mt * 16 + r;
#pragma unroll
        for (int ks = 0; ks < 2; ks++) {
            qh[mt][ks][0] = qh_g[(size_t)nr0 * 16 + ks * 8 + c];
            qh[mt][ks][1] = qh_g[(size_t)(nr0 + 8) * 16 + ks * 8 + c];
            qh[mt][ks][2] = qh_g[(size_t)nr0 * 16 + ks * 8 + 4 + c];
            qh[mt][ks][3] = qh_g[(size_t)(nr0 + 8) * 16 + ks * 8 + 4 + c];
            ql[mt][ks][0] = ql_g[(size_t)nr0 * 16 + ks * 8 + c];
            ql[mt][ks][1] = ql_g[(size_t)(nr0 + 8) * 16 + ks * 8 + c];
            ql[mt][ks][2] = ql_g[(size_t)nr0 * 16 + ks * 8 + 4 + c];
            ql[mt][ks][3] = ql_g[(size_t)(nr0 + 8) * 16 + ks * 8 + 4 + c];
        }
    }
    const float tm = g_tabmax[h];
    float Cc[2][2];
#pragma unroll
    for (int mt = 0; mt < 2; mt++) {
        int nr0 = n0 + qg * 32 + mt * 16 + r;
        Cc[mt][0] = g_smax[bh * NN + nr0] + tm;
        Cc[mt][1] = g_smax[bh * NN + nr0 + 8] + tm;
    }
    const uint32_t* bbp = g_bias + ((size_t)h * NN + n0 + qg * 32) * 512;

    float O[2][4][4] = {};
    float ll[2][2] = {};

    for (int kt = 0; kt < 16; kt++) {
        __syncthreads();
        if (kt < 15) {
            issue(kt + 1, (kt + 1) & 1);
            asm volatile("cp.async.commit_group;");
            asm volatile("cp.async.wait_group 1;");
        } else {
            asm volatile("cp.async.wait_group 0;");
        }
        __syncthreads();

        const uint32_t* Khb = smw + (kt & 1) * ABUF;
        const uint32_t* Klb = Khb + 1280;
        const uint32_t* Vhb = Khb + 2560;
        const uint32_t* Vlb = Khb + 3712;

        // bias prefetch (consumed after MMAs)
        uint32_t bw[2][2][4];
#pragma unroll
        for (int mt = 0; mt < 2; mt++)
#pragma unroll
            for (int half = 0; half < 2; half++)
#pragma unroll
                for (int j = 0; j < 4; j++)
                    bw[mt][half][j] = bbp[(size_t)(mt * 16 + half * 8 + r) * 512 +
                                          kt * 32 + kg * 16 + j * 4 + c];

        // ---- S = Q K^T over this warp's 32 keys (3-plane bf16) ----
        float sc[2][4][4] = {};
#pragma unroll
        for (int j = 0; j < 4; j++) {
            int rowb = (kg * 32 + j * 8 + r) * 20;
#pragma unroll
            for (int ks = 0; ks < 2; ks++) {
                uint32_t bh0 = Khb[rowb + ks * 8 + c], bh1 = Khb[rowb + ks * 8 + 4 + c];
                uint32_t bl0 = Klb[rowb + ks * 8 + c], bl1 = Klb[rowb + ks * 8 + 4 + c];
#pragma unroll
                for (int mt = 0; mt < 2; mt++) {
                    mma_bf16(sc[mt][j], qh[mt][ks][0], qh[mt][ks][1], qh[mt][ks][2], qh[mt][ks][3], bh0, bh1);
                    mma_bf16(sc[mt][j], ql[mt][ks][0], ql[mt][ks][1], ql[mt][ks][2], ql[mt][ks][3], bh0, bh1);
                    mma_bf16(sc[mt][j], qh[mt][ks][0], qh[mt][ks][1], qh[mt][ks][2], qh[mt][ks][3], bl0, bl1);
                }
            }
        }

        // ---- fixed-max softmax: p = exp(S + bias - C) ----
        uint32_t phr[2][4], phr8[2][4], plr[2][4], plr8[2][4];
#pragma unroll
        for (int mt = 0; mt < 2; mt++) {
            float s0 = 0.f, s1 = 0.f;
#pragma unroll
            for (int j = 0; j < 4; j++) {
                float p0 = __expf(sc[mt][j][0] + __uint_as_float(bw[mt][0][j] << 16)         - Cc[mt][0]);
                float p1 = __expf(sc[mt][j][1] + __uint_as_float(bw[mt][0][j] & 0xffff0000u) - Cc[mt][0]);
                float p2 = __expf(sc[mt][j][2] + __uint_as_float(bw[mt][1][j] << 16)         - Cc[mt][1]);
                float p3 = __expf(sc[mt][j][3] + __uint_as_float(bw[mt][1][j] & 0xffff0000u) - Cc[mt][1]);
                s0 += p0 + p1; s1 += p2 + p3;
                bfsplit2(p0, p1, phr[mt][j],  plr[mt][j]);
                bfsplit2(p2, p3, phr8[mt][j], plr8[mt][j]);
            }
            ll[mt][0] += s0; ll[mt][1] += s1;
        }

        // ---- O += P @ V over this warp's 32 keys ----
#pragma unroll
        for (int kk = 0; kk < 2; kk++) {
#pragma unroll
            for (int jd = 0; jd < 4; jd++) {
                int w0 = (jd * 8 + r) * 36 + kg * 16 + kk * 8 + c;
                uint32_t vh0 = Vhb[w0], vh1 = Vhb[w0 + 4];
                uint32_t vl0 = Vlb[w0], vl1 = Vlb[w0 + 4];
#pragma unroll
                for (int mt = 0; mt < 2; mt++) {
                    mma_bf16(O[mt][jd], phr[mt][2 * kk], phr8[mt][2 * kk],
                             phr[mt][2 * kk + 1], phr8[mt][2 * kk + 1], vh0, vh1);
                    mma_bf16(O[mt][jd], plr[mt][2 * kk], plr8[mt][2 * kk],
                             plr[mt][2 * kk + 1], plr8[mt][2 * kk + 1], vh0, vh1);
                    mma_bf16(O[mt][jd], phr[mt][2 * kk], phr8[mt][2 * kk],
                             phr[mt][2 * kk + 1], phr8[mt][2 * kk + 1], vl0, vl1);
                }
            }
        }
    }

    // ---- merge the two key-halves, normalize, write ----
#pragma unroll
    for (int mt = 0; mt < 2; mt++)
#pragma unroll
        for (int half = 0; half < 2; half++) {
            ll[mt][half] += __shfl_xor_sync(0xffffffffu, ll[mt][half], 1);
            ll[mt][half] += __shfl_xor_sync(0xffffffffu, ll[mt][half], 2);
        }

    float* xb = (float*)smw;                 // loop done; buffers reusable
    int slot = qg * (32 * 37) + lane * 37;
    if (kg == 1) {
#pragma unroll
        for (int mt = 0; mt < 2; mt++) {
#pragma unroll
            for (int jd = 0; jd < 4; jd++)
#pragma unroll
                for (int q = 0; q < 4; q++)
                    xb[slot + mt * 16 + jd * 4 + q] = O[mt][jd][q];
            xb[slot + 32 + mt * 2 + 0] = ll[mt][0];
            xb[slot + 32 + mt * 2 + 1] = ll[mt][1];
        }
    }
    __syncthreads();
    if (kg == 0) {
#pragma unroll
        for (int mt = 0; mt < 2; mt++) {
            float lt0 = ll[mt][0] + xb[slot + 32 + mt * 2 + 0];
            float lt1 = ll[mt][1] + xb[slot + 32 + mt * 2 + 1];
            float i0 = 1.f / lt0, i1 = 1.f / lt1;
            int nr0 = n0 + qg * 32 + mt * 16 + r;
#pragma unroll
            for (int jd = 0; jd < 4; jd++) {
                float o0 = O[mt][jd][0] + xb[slot + mt * 16 + jd * 4 + 0];
                float o1 = O[mt][jd][1] + xb[slot + mt * 16 + jd * 4 + 1];
                float o2 = O[mt][jd][2] + xb[slot + mt * 16 + jd * 4 + 2];
                float o3 = O[mt][jd][3] + xb[slot + mt * 16 + jd * 4 + 3];
                int col = h * HD + jd * 8 + 2 * c;
                *(float2*)&out[(size_t)(b * NN + nr0) * CDIM + col] =
                    make_float2(o0 * i0, o1 * i0);
                *(float2*)&out[(size_t)(b * NN + nr0 + 8) * CDIM + col] =
                    make_float2(o2 * i1, o3 * i1);
            }
        }
    }
}

// ---------------- launch ------------------------------------------------------
extern "C" void kernel_launch(void* const* d_in, const int* in_sizes, int n_in,
                              void* d_out, int out_size) {
    int s = (n_in >= 15) ? 0 : -2;
    const float* x       = (const float*)d_in[0];
    const int*   rpi     = (const int*)  d_in[3 + s];
    const float* coords  = (const float*)d_in[4 + s];
    const float* qkv_w   = (const float*)d_in[5 + s];
    const float* qkv_b   = (const float*)d_in[6 + s];
    const float* qe      = (const float*)d_in[7 + s];
    const float* temp    = (const float*)d_in[8 + s];
    const float* proj_w  = (const float*)d_in[9 + s];
    const float* proj_b  = (const float*)d_in[10 + s];
    const float* fc1w    = (const float*)d_in[11 + s];
    const float* fc1b    = (const float*)d_in[12 + s];
    const float* fc2w    = (const float*)d_in[13 + s];
    const float* fc2b    = (const float*)d_in[14 + s];
    float* out = (float*)d_out;

    float* p_ao;
    cudaGetSymbolAddress((void**)&p_ao, g_ao);

    cpb_kernel<<<(TABLE_SZ + 31) / 32, 256>>>(coords, fc1w, fc1b, fc2w, fc2b);
    bias_expand<<<NHEADS * 64, 256>>>(rpi);

    size_t gemm_smem = (2 * 128 * 20 + 2 * 64 * 20) * sizeof(uint32_t);   // 30.7 KB
    cudaFuncSetAttribute(gemm_qkv_fused, cudaFuncAttributeMaxDynamicSharedMemorySize, (int)gemm_smem);
    cudaFuncSetAttribute(gemm_tc, cudaFuncAttributeMaxDynamicSharedMemorySize, (int)gemm_smem);

    gemm_qkv_fused<<<dim3(768 / 64, (BB * NN) / 128), 256, gemm_smem>>>(
        x, qkv_w, qkv_b, qe, temp);

    {
        size_t smem = 2 * ABUF * sizeof(uint32_t);    // 38.9 KB
        cudaFuncSetAttribute(attn_tc, cudaFuncAttributeMaxDynamicSharedMemorySize, (int)smem);
        attn_tc<<<dim3(16, NHEADS, BB), 128, smem>>>(p_ao);
    }

    gemm_tc<<<dim3(CDIM / 64, (BB * NN) / 128), 256, gemm_smem>>>(
        p_ao, proj_w, proj_b, out, BB * NN, CDIM, CDIM);
}

// round 10
// speedup vs baseline: 1.2847x; 1.0712x over previous
#include <cuda_runtime.h>
#include <math.h>
#include <stdint.h>

#define BB      8
#define NHEADS  8
#define HD      32
#define NN      1024
#define CDIM    256
#define TABLE_SZ 3969
#define CPBH    512
#define LOG2E   1.4426950408889634f

// ---------------- scratch (bf16 hi/lo word layouts) -------------------------
__device__ __align__(16) uint32_t g_q2h[BB * NHEADS * NN * 16];
__device__ __align__(16) uint32_t g_q2l[BB * NHEADS * NN * 16];
__device__ __align__(16) uint32_t g_kh [BB * NHEADS * NN * 16];
__device__ __align__(16) uint32_t g_kl [BB * NHEADS * NN * 16];
__device__ __align__(16) uint32_t g_vth[BB * NHEADS * HD * (NN / 2)];
__device__ __align__(16) uint32_t g_vtl[BB * NHEADS * HD * (NN / 2)];
__device__ __align__(16) uint32_t g_bias[NHEADS * NN * (NN / 2)];    // bf16x2 (base-2 units)
__device__ float g_tab[NHEADS * TABLE_SZ];     // scaled by log2e
__device__ float g_tabmax[NHEADS];
__device__ float g_smax[BB * NHEADS * NN];     // ||qs_n|| (base-2 units)
__device__ float g_ao [BB * NN * CDIM];

// ---------------- helpers -----------------------------------------------------
__device__ __forceinline__ uint32_t bf16x2(float lo, float hi) {
    uint32_t d;
    asm("cvt.rn.bf16x2.f32 %0, %1, %2;" : "=r"(d) : "f"(hi), "f"(lo));
    return d;
}
__device__ __forceinline__ void bfsplit2(float x0, float x1, uint32_t &hi, uint32_t &lo) {
    uint32_t h = bf16x2(x0, x1);
    float r0 = x0 - __uint_as_float(h << 16);
    float r1 = x1 - __uint_as_float(h & 0xffff0000u);
    hi = h;
    lo = bf16x2(r0, r1);
}
__device__ __forceinline__ float ex2f(float x) {
    float y;
    asm("ex2.approx.f32 %0, %1;" : "=f"(y) : "f"(x));
    return y;
}
__device__ __forceinline__ void mma_bf16(float c[4],
                                         uint32_t a0, uint32_t a1, uint32_t a2, uint32_t a3,
                                         uint32_t b0, uint32_t b1) {
    asm volatile(
        "mma.sync.aligned.m16n8k16.row.col.f32.bf16.bf16.f32 "
        "{%0,%1,%2,%3}, {%4,%5,%6,%7}, {%8,%9}, {%0,%1,%2,%3};"
        : "+f"(c[0]), "+f"(c[1]), "+f"(c[2]), "+f"(c[3])
        : "r"(a0), "r"(a1), "r"(a2), "r"(a3), "r"(b0), "r"(b1));
}
__device__ __forceinline__ void cp16(uint32_t dst, const void* src) {
    asm volatile("cp.async.cg.shared.global [%0], [%1], 16;" :: "r"(dst), "l"(src));
}

// ---------------- CPB MLP (SMEM-staged weights, warp-per-entry) --------------
__global__ __launch_bounds__(256) void cpb_kernel(const float* __restrict__ coords,
                                                  const float* __restrict__ fc1w,
                                                  const float* __restrict__ fc1b,
                                                  const float* __restrict__ fc2w,
                                                  const float* __restrict__ fc2b) {
    __shared__ float s_w1[CPBH * 2];
    __shared__ float s_b1[CPBH];
    __shared__ float s_w2[NHEADS * CPBH];
    const int tid = threadIdx.x;
    for (int i = tid; i < CPBH * 2; i += 256) s_w1[i] = fc1w[i];
    for (int i = tid; i < CPBH; i += 256) s_b1[i] = fc1b[i];
    for (int i = tid; i < NHEADS * CPBH; i += 256) s_w2[i] = fc2w[i];
    __syncthreads();
    const int warp = tid >> 5, lane = tid & 31;
#pragma unroll
    for (int e = 0; e < 4; e++) {
        int t = blockIdx.x * 32 + warp * 4 + e;
        if (t >= TABLE_SZ) continue;
        float c0 = coords[2 * t], c1 = coords[2 * t + 1];
        float acc[NHEADS];
#pragma unroll
        for (int h = 0; h < NHEADS; h++) acc[h] = 0.f;
#pragma unroll 4
        for (int j = lane; j < CPBH; j += 32) {
            float hv = fmaxf(c0 * s_w1[2 * j] + c1 * s_w1[2 * j + 1] + s_b1[j], 0.f);
#pragma unroll
            for (int h = 0; h < NHEADS; h++) acc[h] += hv * s_w2[h * CPBH + j];
        }
#pragma unroll
        for (int h = 0; h < NHEADS; h++) {
#pragma unroll
            for (int o = 16; o; o >>= 1) acc[h] += __shfl_xor_sync(0xffffffffu, acc[h], o);
            if (lane == 0) g_tab[h * TABLE_SZ + t] = (acc[h] + fc2b[h]) * LOG2E;
        }
    }
}

// ---------------- bias expand + per-head max ----------------------------------
__global__ __launch_bounds__(256) void bias_expand(const int* __restrict__ rpi) {
    __shared__ float tab_s[TABLE_SZ];
    __shared__ float redm[8];
    int h = blockIdx.x >> 6;
    int chunk = blockIdx.x & 63;
    for (int i = threadIdx.x; i < TABLE_SZ; i += 256) tab_s[i] = g_tab[h * TABLE_SZ + i];
    __syncthreads();
    if (chunk == 0) {
        float m = -1e30f;
        for (int i = threadIdx.x; i < TABLE_SZ; i += 256) m = fmaxf(m, tab_s[i]);
#pragma unroll
        for (int o = 16; o; o >>= 1) m = fmaxf(m, __shfl_xor_sync(0xffffffffu, m, o));
        if ((threadIdx.x & 31) == 0) redm[threadIdx.x >> 5] = m;
        __syncthreads();
        if (threadIdx.x == 0) {
            float mm = redm[0];
            for (int w = 1; w < 8; w++) mm = fmaxf(mm, redm[w]);
            g_tabmax[h] = mm;
        }
    }
    for (int i = threadIdx.x; i < 16 * 512; i += 256) {
        int nl = i >> 9, mw = i & 511;
        int n = chunk * 16 + nl;
        int2 id = *(const int2*)&rpi[(size_t)n * NN + 2 * mw];
        g_bias[((size_t)h * NN + n) * 512 + mw] = bf16x2(tab_s[id.x], tab_s[id.y]);
    }
}

// ---------------- fused qkv GEMM + l2norm + split -> word layouts ------------
__global__ __launch_bounds__(256) void gemm_qkv_fused(
        const float* __restrict__ A, const float* __restrict__ W,
        const float* __restrict__ bias,
        const float* __restrict__ qe, const float* __restrict__ temp) {
    extern __shared__ uint32_t smg[];
    uint32_t* Ah = smg;               // [128][20]
    uint32_t* Al = Ah + 128 * 20;
    uint32_t* Wh = Al + 128 * 20;     // [64][20]
    uint32_t* Wl = Wh + 64 * 20;
    const int bm = blockIdx.y * 128, bn = blockIdx.x * 64;
    const int tid = threadIdx.x, lane = tid & 31, warp = tid >> 5;
    const int wm = (warp >> 1) * 32, wn = (warp & 1) * 32;
    const int r = lane >> 2, c = lane & 3;
    const int K = CDIM;

    float acc[2][4][4];
#pragma unroll
    for (int mt = 0; mt < 2; mt++)
#pragma unroll
        for (int nt = 0; nt < 4; nt++)
#pragma unroll
            for (int q = 0; q < 4; q++) acc[mt][nt][q] = 0.f;

    float4 pa[4], pw[2];
#pragma unroll
    for (int i = 0; i < 4; i++) {
        int v = tid + i * 256; int row = v >> 3, kq = (v & 7) * 4;
        pa[i] = *(const float4*)&A[(size_t)(bm + row) * K + kq];
    }
#pragma unroll
    for (int i = 0; i < 2; i++) {
        int v = tid + i * 256; int row = v >> 3, kq = (v & 7) * 4;
        pw[i] = *(const float4*)&W[(size_t)(bn + row) * K + kq];
    }

    for (int k0 = 0; k0 < K; k0 += 32) {
#pragma unroll
        for (int i = 0; i < 4; i++) {
            int v = tid + i * 256; int row = v >> 3, kq = (v & 7) * 4;
            uint32_t h, l;
            bfsplit2(pa[i].x, pa[i].y, h, l);
            Ah[row * 20 + (kq >> 1)] = h;  Al[row * 20 + (kq >> 1)] = l;
            bfsplit2(pa[i].z, pa[i].w, h, l);
            Ah[row * 20 + (kq >> 1) + 1] = h;  Al[row * 20 + (kq >> 1) + 1] = l;
        }
#pragma unroll
        for (int i = 0; i < 2; i++) {
            int v = tid + i * 256; int row = v >> 3, kq = (v & 7) * 4;
            uint32_t h, l;
            bfsplit2(pw[i].x, pw[i].y, h, l);
            Wh[row * 20 + (kq >> 1)] = h;  Wl[row * 20 + (kq >> 1)] = l;
            bfsplit2(pw[i].z, pw[i].w, h, l);
            Wh[row * 20 + (kq >> 1) + 1] = h;  Wl[row * 20 + (kq >> 1) + 1] = l;
        }
        __syncthreads();
        if (k0 + 32 < K) {
#pragma unroll
            for (int i = 0; i < 4; i++) {
                int v = tid + i * 256; int row = v >> 3, kq = (v & 7) * 4;
                pa[i] = *(const float4*)&A[(size_t)(bm + row) * K + k0 + 32 + kq];
            }
#pragma unroll
            for (int i = 0; i < 2; i++) {
                int v = tid + i * 256; int row = v >> 3, kq = (v & 7) * 4;
                pw[i] = *(const float4*)&W[(size_t)(bn + row) * K + k0 + 32 + kq];
            }
        }
#pragma unroll
        for (int kt = 0; kt < 2; kt++) {
            uint32_t ah[2][4], al[2][4];
#pragma unroll
            for (int mt = 0; mt < 2; mt++) {
                int r0 = (wm + mt * 16 + r) * 20 + kt * 8 + c;
                int r1 = r0 + 8 * 20;
                ah[mt][0] = Ah[r0];     al[mt][0] = Al[r0];
                ah[mt][1] = Ah[r1];     al[mt][1] = Al[r1];
                ah[mt][2] = Ah[r0 + 4]; al[mt][2] = Al[r0 + 4];
                ah[mt][3] = Ah[r1 + 4]; al[mt][3] = Al[r1 + 4];
            }
#pragma unroll
            for (int nt = 0; nt < 4; nt++) {
                int w0 = (wn + nt * 8 + r) * 20 + kt * 8 + c;
                uint32_t bh0 = Wh[w0], bh1 = Wh[w0 + 4];
                uint32_t bl0 = Wl[w0], bl1 = Wl[w0 + 4];
#pragma unroll
                for (int mt = 0; mt < 2; mt++) {
                    mma_bf16(acc[mt][nt], ah[mt][0], ah[mt][1], ah[mt][2], ah[mt][3], bh0, bh1);
                    mma_bf16(acc[mt][nt], al[mt][0], al[mt][1], al[mt][2], al[mt][3], bh0, bh1);
                    mma_bf16(acc[mt][nt], ah[mt][0], ah[mt][1], ah[mt][2], ah[mt][3], bl0, bl1);
                }
            }
        }
        __syncthreads();
    }

    // ---- fused epilogue ----
    const int col_base = bn + wn;
    const int region = col_base >> 8;             // 0=q, 1=k, 2=v
    const int head = (col_base >> 5) & 7;
    float scale_h = 0.f, qe0[4], qe1[4];
    if (region == 0) {
        scale_h = log1pf(expf(temp[head])) * logf(1024.0f) * LOG2E;
#pragma unroll
        for (int nt = 0; nt < 4; nt++) {
            qe0[nt] = qe[head * HD + nt * 8 + 2 * c];
            qe1[nt] = qe[head * HD + nt * 8 + 2 * c + 1];
        }
    }
#pragma unroll
    for (int mt = 0; mt < 2; mt++) {
#pragma unroll
        for (int half = 0; half < 2; half++) {
            int row = bm + wm + mt * 16 + r + half * 8;
            int bq = row >> 10, n = row & 1023;
            float v0[4], v1[4];
#pragma unroll
            for (int nt = 0; nt < 4; nt++) {
                int cg = col_base + nt * 8 + 2 * c;
                v0[nt] = acc[mt][nt][half * 2]     + bias[cg];
                v1[nt] = acc[mt][nt][half * 2 + 1] + bias[cg + 1];
            }
            if (region < 2) {
                float ss = 0.f;
#pragma unroll
                for (int nt = 0; nt < 4; nt++) ss += v0[nt] * v0[nt] + v1[nt] * v1[nt];
                ss += __shfl_xor_sync(0xffffffffu, ss, 1);
                ss += __shfl_xor_sync(0xffffffffu, ss, 2);
                float inv = 1.f / fmaxf(sqrtf(ss), 1e-12f);
                size_t base = ((size_t)(bq * 8 + head) * NN + n) * 16;
                float ss2 = 0.f;
#pragma unroll
                for (int nt = 0; nt < 4; nt++) {
                    float a = v0[nt] * inv, bv = v1[nt] * inv;
                    if (region == 0) {
                        a  = (a  + qe0[nt]) * scale_h;
                        bv = (bv + qe1[nt]) * scale_h;
                        ss2 += a * a + bv * bv;
                    }
                    uint32_t hh, ll;
                    bfsplit2(a, bv, hh, ll);
                    size_t w = base + nt * 4 + c;
                    if (region == 0) { g_q2h[w] = hh; g_q2l[w] = ll; }
                    else             { g_kh[w]  = hh; g_kl[w]  = ll; }
                }
                if (region == 0) {
                    ss2 += __shfl_xor_sync(0xffffffffu, ss2, 1);
                    ss2 += __shfl_xor_sync(0xffffffffu, ss2, 2);
                    if (c == 0)
                        g_smax[(size_t)(bq * 8 + head) * NN + n] = sqrtf(ss2);
                }
            } else {
                size_t bh = (size_t)(bq * 8 + head);
                int np = n >> 1;
                bool evenr = ((r & 1) == 0);
#pragma unroll
                for (int nt = 0; nt < 4; nt++) {
                    float ge = __shfl_xor_sync(0xffffffffu, v0[nt], 4);
                    float go = __shfl_xor_sync(0xffffffffu, v1[nt], 4);
                    int dloc = nt * 8 + 2 * c;
                    float p0, p1; int d;
                    if (evenr) { p0 = v0[nt]; p1 = ge;     d = dloc; }
                    else       { p0 = go;     p1 = v1[nt]; d = dloc + 1; }
                    uint32_t hh, ll;
                    bfsplit2(p0, p1, hh, ll);
                    size_t w = (bh * HD + d) * 512 + np;
                    g_vth[w] = hh; g_vtl[w] = ll;
                }
            }
        }
    }
}

// ---------------- proj GEMM (inline convert + reg prefetch) ------------------
__global__ void __launch_bounds__(256) gemm_tc(const float* __restrict__ A,
                                               const float* __restrict__ W,
                                               const float* __restrict__ bias,
                                               float* __restrict__ C,
                                               int M, int N, int K) {
    extern __shared__ uint32_t smg[];
    uint32_t* Ah = smg;
    uint32_t* Al = Ah + 128 * 20;
    uint32_t* Wh = Al + 128 * 20;
    uint32_t* Wl = Wh + 64 * 20;
    const int bm = blockIdx.y * 128, bn = blockIdx.x * 64;
    const int tid = threadIdx.x, lane = tid & 31, warp = tid >> 5;
    const int wm = (warp >> 1) * 32, wn = (warp & 1) * 32;
    const int r = lane >> 2, c = lane & 3;

    float acc[2][4][4];
#pragma unroll
    for (int mt = 0; mt < 2; mt++)
#pragma unroll
        for (int nt = 0; nt < 4; nt++)
#pragma unroll
            for (int q = 0; q < 4; q++) acc[mt][nt][q] = 0.f;

    float4 pa[4], pw[2];
#pragma unroll
    for (int i = 0; i < 4; i++) {
        int v = tid + i * 256; int row = v >> 3, kq = (v & 7) * 4;
        pa[i] = *(const float4*)&A[(size_t)(bm + row) * K + kq];
    }
#pragma unroll
    for (int i = 0; i < 2; i++) {
        int v = tid + i * 256; int row = v >> 3, kq = (v & 7) * 4;
        pw[i] = *(const float4*)&W[(size_t)(bn + row) * K + kq];
    }

    for (int k0 = 0; k0 < K; k0 += 32) {
#pragma unroll
        for (int i = 0; i < 4; i++) {
            int v = tid + i * 256; int row = v >> 3, kq = (v & 7) * 4;
            uint32_t h, l;
            bfsplit2(pa[i].x, pa[i].y, h, l);
            Ah[row * 20 + (kq >> 1)] = h;  Al[row * 20 + (kq >> 1)] = l;
            bfsplit2(pa[i].z, pa[i].w, h, l);
            Ah[row * 20 + (kq >> 1) + 1] = h;  Al[row * 20 + (kq >> 1) + 1] = l;
        }
#pragma unroll
        for (int i = 0; i < 2; i++) {
            int v = tid + i * 256; int row = v >> 3, kq = (v & 7) * 4;
            uint32_t h, l;
            bfsplit2(pw[i].x, pw[i].y, h, l);
            Wh[row * 20 + (kq >> 1)] = h;  Wl[row * 20 + (kq >> 1)] = l;
            bfsplit2(pw[i].z, pw[i].w, h, l);
            Wh[row * 20 + (kq >> 1) + 1] = h;  Wl[row * 20 + (kq >> 1) + 1] = l;
        }
        __syncthreads();
        if (k0 + 32 < K) {
#pragma unroll
            for (int i = 0; i < 4; i++) {
                int v = tid + i * 256; int row = v >> 3, kq = (v & 7) * 4;
                pa[i] = *(const float4*)&A[(size_t)(bm + row) * K + k0 + 32 + kq];
            }
#pragma unroll
            for (int i = 0; i < 2; i++) {
                int v = tid + i * 256; int row = v >> 3, kq = (v & 7) * 4;
                pw[i] = *(const float4*)&W[(size_t)(bn + row) * K + k0 + 32 + kq];
            }
        }
#pragma unroll
        for (int kt = 0; kt < 2; kt++) {
            uint32_t ah[2][4], al[2][4];
#pragma unroll
            for (int mt = 0; mt < 2; mt++) {
                int r0 = (wm + mt * 16 + r) * 20 + kt * 8 + c;
                int r1 = r0 + 8 * 20;
                ah[mt][0] = Ah[r0];     al[mt][0] = Al[r0];
                ah[mt][1] = Ah[r1];     al[mt][1] = Al[r1];
                ah[mt][2] = Ah[r0 + 4]; al[mt][2] = Al[r0 + 4];
                ah[mt][3] = Ah[r1 + 4]; al[mt][3] = Al[r1 + 4];
            }
#pragma unroll
            for (int nt = 0; nt < 4; nt++) {
                int w0 = (wn + nt * 8 + r) * 20 + kt * 8 + c;
                uint32_t bh0 = Wh[w0], bh1 = Wh[w0 + 4];
                uint32_t bl0 = Wl[w0], bl1 = Wl[w0 + 4];
#pragma unroll
                for (int mt = 0; mt < 2; mt++) {
                    mma_bf16(acc[mt][nt], ah[mt][0], ah[mt][1], ah[mt][2], ah[mt][3], bh0, bh1);
                    mma_bf16(acc[mt][nt], al[mt][0], al[mt][1], al[mt][2], al[mt][3], bh0, bh1);
                    mma_bf16(acc[mt][nt], ah[mt][0], ah[mt][1], ah[mt][2], ah[mt][3], bl0, bl1);
                }
            }
        }
        __syncthreads();
    }
#pragma unroll
    for (int mt = 0; mt < 2; mt++) {
        int row0 = bm + wm + mt * 16 + r;
        int row1 = row0 + 8;
#pragma unroll
        for (int nt = 0; nt < 4; nt++) {
            int n = bn + wn + nt * 8 + 2 * c;
            float b0 = bias[n], b1 = bias[n + 1];
            *(float2*)&C[(size_t)row0 * N + n] = make_float2(acc[mt][nt][0] + b0, acc[mt][nt][1] + b1);
            *(float2*)&C[(size_t)row1 * N + n] = make_float2(acc[mt][nt][2] + b0, acc[mt][nt][3] + b1);
        }
    }
}

// ---------------- attention: 2x2 (query,key) warp split ----------------------
// Fixed-max base-2 softmax; single-plane P for PV (l from rounded P).
#define ABUF 4864   // words: Kh 1280 | Kl 1280 | Vh 1152 | Vl 1152

__global__ __launch_bounds__(128, 4) void attn_tc(float* __restrict__ out) {
    extern __shared__ uint32_t smw[];

    const int n0 = blockIdx.x * 64;
    const int h  = blockIdx.y;
    const int b  = blockIdx.z;
    const int tid = threadIdx.x, lane = tid & 31, warp = tid >> 5;
    const int qg = warp >> 1, kg = warp & 1;
    const int r = lane >> 2, c = lane & 3;
    const size_t bh = (size_t)(b * NHEADS + h);

    const uint32_t* kh_g  = g_kh  + bh * NN * 16;
    const uint32_t* kl_g  = g_kl  + bh * NN * 16;
    const uint32_t* vth_g = g_vth + bh * HD * 512;
    const uint32_t* vtl_g = g_vtl + bh * HD * 512;

    auto issue = [&](int kt, int buf) {
        uint32_t s0 = (uint32_t)__cvta_generic_to_shared(smw + buf * ABUF);
#pragma unroll
        for (int i = 0; i < 4; i++) {
            int v = tid + i * 128;
            int plane = v >> 8, rem = v & 255;
            int row = rem >> 2, cq = (rem & 3) * 4;
            const uint32_t* src = (plane ? kl_g : kh_g) + (size_t)(kt * 64 + row) * 16 + cq;
            cp16(s0 + (plane * 1280 + row * 20 + cq) * 4, src);
        }
#pragma unroll
        for (int i = 0; i < 4; i++) {
            int v = tid + i * 128;
            int plane = v >> 8, rem = v & 255;
            int d = rem >> 3, cq = (rem & 7) * 4;
            const uint32_t* src = (plane ? vtl_g : vth_g) + (size_t)d * 512 + kt * 32 + cq;
            cp16(s0 + (2560 + plane * 1152 + d * 36 + cq) * 4, src);
        }
    };

    issue(0, 0);
    asm volatile("cp.async.commit_group;");

    // Q fragments: rows n0 + qg*32 + mt*16 + {r, r+8}
    const uint32_t* qh_g = g_q2h + bh * NN * 16;
    const uint32_t* ql_g = g_q2l + bh * NN * 16;
    uint32_t qh[2][2][4], ql[2][2][4];
#pragma unroll
    for (int mt = 0; mt < 2; mt++) {
        int nr0 = n0 + qg * 32 + mt * 16 + r;
#pragma unroll
        for (int ks = 0; ks < 2; ks++) {
            qh[mt][ks][0] = qh_g[(size_t)nr0 * 16 + ks * 8 + c];
            qh[mt][ks][1] = qh_g[(size_t)(nr0 + 8) * 16 + ks * 8 + c];
            qh[mt][ks][2] = qh_g[(size_t)nr0 * 16 + ks * 8 + 4 + c];
            qh[mt][ks][3] = qh_g[(size_t)(nr0 + 8) * 16 + ks * 8 + 4 + c];
            ql[mt][ks][0] = ql_g[(size_t)nr0 * 16 + ks * 8 + c];
            ql[mt][ks][1] = ql_g[(size_t)(nr0 + 8) * 16 + ks * 8 + c];
            ql[mt][ks][2] = ql_g[(size_t)nr0 * 16 + ks * 8 + 4 + c];
            ql[mt][ks][3] = ql_g[(size_t)(nr0 + 8) * 16 + ks * 8 + 4 + c];
        }
    }
    const float tm = g_tabmax[h];
    float Cc[2][2];
#pragma unroll
    for (int mt = 0; mt < 2; mt++) {
        int nr0 = n0 + qg * 32 + mt * 16 + r;
        Cc[mt][0] = g_smax[bh * NN + nr0] + tm;
        Cc[mt][1] = g_smax[bh * NN + nr0 + 8] + tm;
    }
    // hoisted bias row pointers (advance by kt*32 each tile)
    const uint32_t* bp[2][2];
#pragma unroll
    for (int mt = 0; mt < 2; mt++)
#pragma unroll
        for (int half = 0; half < 2; half++)
            bp[mt][half] = g_bias + ((size_t)h * NN + n0 + qg * 32 + mt * 16 + half * 8 + r) * 512
                           + kg * 16 + c;

    float O[2][4][4] = {};
    float ll[2][2] = {};

    for (int kt = 0; kt < 16; kt++) {
        __syncthreads();
        if (kt < 15) {
            issue(kt + 1, (kt + 1) & 1);
            asm volatile("cp.async.commit_group;");
            asm volatile("cp.async.wait_group 1;");
        } else {
            asm volatile("cp.async.wait_group 0;");
        }
        __syncthreads();

        const uint32_t* Khb = smw + (kt & 1) * ABUF;
        const uint32_t* Klb = Khb + 1280;
        const uint32_t* Vhb = Khb + 2560;
        const uint32_t* Vlb = Khb + 3712;

        // bias prefetch (consumed after MMAs)
        uint32_t bw[2][2][4];
#pragma unroll
        for (int mt = 0; mt < 2; mt++)
#pragma unroll
            for (int half = 0; half < 2; half++)
#pragma unroll
                for (int j = 0; j < 4; j++)
                    bw[mt][half][j] = bp[mt][half][kt * 32 + j * 4];

        // ---- S = Q K^T over this warp's 32 keys (3-plane bf16) ----
        float sc[2][4][4] = {};
#pragma unroll
        for (int j = 0; j < 4; j++) {
            int rowb = (kg * 32 + j * 8 + r) * 20;
#pragma unroll
            for (int ks = 0; ks < 2; ks++) {
                uint32_t bh0 = Khb[rowb + ks * 8 + c], bh1 = Khb[rowb + ks * 8 + 4 + c];
                uint32_t bl0 = Klb[rowb + ks * 8 + c], bl1 = Klb[rowb + ks * 8 + 4 + c];
#pragma unroll
                for (int mt = 0; mt < 2; mt++) {
                    mma_bf16(sc[mt][j], qh[mt][ks][0], qh[mt][ks][1], qh[mt][ks][2], qh[mt][ks][3], bh0, bh1);
                    mma_bf16(sc[mt][j], ql[mt][ks][0], ql[mt][ks][1], ql[mt][ks][2], ql[mt][ks][3], bh0, bh1);
                    mma_bf16(sc[mt][j], qh[mt][ks][0], qh[mt][ks][1], qh[mt][ks][2], qh[mt][ks][3], bl0, bl1);
                }
            }
        }

        // ---- fixed-max base-2 softmax: p = exp2(S + bias - C); single plane ----
        uint32_t phr[2][4], phr8[2][4];
#pragma unroll
        for (int mt = 0; mt < 2; mt++) {
            float s0 = 0.f, s1 = 0.f;
#pragma unroll
            for (int j = 0; j < 4; j++) {
                float p0 = ex2f(sc[mt][j][0] + __uint_as_float(bw[mt][0][j] << 16)         - Cc[mt][0]);
                float p1 = ex2f(sc[mt][j][1] + __uint_as_float(bw[mt][0][j] & 0xffff0000u) - Cc[mt][0]);
                float p2 = ex2f(sc[mt][j][2] + __uint_as_float(bw[mt][1][j] << 16)         - Cc[mt][1]);
                float p3 = ex2f(sc[mt][j][3] + __uint_as_float(bw[mt][1][j] & 0xffff0000u) - Cc[mt][1]);
                uint32_t w01 = bf16x2(p0, p1);
                uint32_t w23 = bf16x2(p2, p3);
                phr[mt][j]  = w01;
                phr8[mt][j] = w23;
                // l from the ROUNDED P so O/l stays a convex combination
                s0 += __uint_as_float(w01 << 16) + __uint_as_float(w01 & 0xffff0000u);
                s1 += __uint_as_float(w23 << 16) + __uint_as_float(w23 & 0xffff0000u);
            }
            ll[mt][0] += s0; ll[mt][1] += s1;
        }

        // ---- O += P @ V over this warp's 32 keys (Ph*Vh + Ph*Vl) ----
#pragma unroll
        for (int kk = 0; kk < 2; kk++) {
#pragma unroll
            for (int jd = 0; jd < 4; jd++) {
                int w0 = (jd * 8 + r) * 36 + kg * 16 + kk * 8 + c;
                uint32_t vh0 = Vhb[w0], vh1 = Vhb[w0 + 4];
                uint32_t vl0 = Vlb[w0], vl1 = Vlb[w0 + 4];
#pragma unroll
                for (int mt = 0; mt < 2; mt++) {
                    mma_bf16(O[mt][jd], phr[mt][2 * kk], phr8[mt][2 * kk],
                             phr[mt][2 * kk + 1], phr8[mt][2 * kk + 1], vh0, vh1);
                    mma_bf16(O[mt][jd], phr[mt][2 * kk], phr8[mt][2 * kk],
                             phr[mt][2 * kk + 1], phr8[mt][2 * kk + 1], vl0, vl1);
                }
            }
        }
    }

    // ---- merge the two key-halves, normalize, write ----
#pragma unroll
    for (int mt = 0; mt < 2; mt++)
#pragma unroll
        for (int half = 0; half < 2; half++) {
            ll[mt][half] += __shfl_xor_sync(0xffffffffu, ll[mt][half], 1);
            ll[mt][half] += __shfl_xor_sync(0xffffffffu, ll[mt][half], 2);
        }

    float* xb = (float*)smw;                 // loop done; buffers reusable
    int slot = qg * (32 * 37) + lane * 37;
    if (kg == 1) {
#pragma unroll
        for (int mt = 0; mt < 2; mt++) {
#pragma unroll
            for (int jd = 0; jd < 4; jd++)
#pragma unroll
                for (int q = 0; q < 4; q++)
                    xb[slot + mt * 16 + jd * 4 + q] = O[mt][jd][q];
            xb[slot + 32 + mt * 2 + 0] = ll[mt][0];
            xb[slot + 32 + mt * 2 + 1] = ll[mt][1];
        }
    }
    __syncthreads();
    if (kg == 0) {
#pragma unroll
        for (int mt = 0; mt < 2; mt++) {
            float lt0 = ll[mt][0] + xb[slot + 32 + mt * 2 + 0];
            float lt1 = ll[mt][1] + xb[slot + 32 + mt * 2 + 1];
            float i0 = 1.f / lt0, i1 = 1.f / lt1;
            int nr0 = n0 + qg * 32 + mt * 16 + r;
#pragma unroll
            for (int jd = 0; jd < 4; jd++) {
                float o0 = O[mt][jd][0] + xb[slot + mt * 16 + jd * 4 + 0];
                float o1 = O[mt][jd][1] + xb[slot + mt * 16 + jd * 4 + 1];
                float o2 = O[mt][jd][2] + xb[slot + mt * 16 + jd * 4 + 2];
                float o3 = O[mt][jd][3] + xb[slot + mt * 16 + jd * 4 + 3];
                int col = h * HD + jd * 8 + 2 * c;
                *(float2*)&out[(size_t)(b * NN + nr0) * CDIM + col] =
                    make_float2(o0 * i0, o1 * i0);
                *(float2*)&out[(size_t)(b * NN + nr0 + 8) * CDIM + col] =
                    make_float2(o2 * i1, o3 * i1);
            }
        }
    }
}

// ---------------- launch ------------------------------------------------------
extern "C" void kernel_launch(void* const* d_in, const int* in_sizes, int n_in,
                              void* d_out, int out_size) {
    int s = (n_in >= 15) ? 0 : -2;
    const float* x       = (const float*)d_in[0];
    const int*   rpi     = (const int*)  d_in[3 + s];
    const float* coords  = (const float*)d_in[4 + s];
    const float* qkv_w   = (const float*)d_in[5 + s];
    const float* qkv_b   = (const float*)d_in[6 + s];
    const float* qe      = (const float*)d_in[7 + s];
    const float* temp    = (const float*)d_in[8 + s];
    const float* proj_w  = (const float*)d_in[9 + s];
    const float* proj_b  = (const float*)d_in[10 + s];
    const float* fc1w    = (const float*)d_in[11 + s];
    const float* fc1b    = (const float*)d_in[12 + s];
    const float* fc2w    = (const float*)d_in[13 + s];
    const float* fc2b    = (const float*)d_in[14 + s];
    float* out = (float*)d_out;

    float* p_ao;
    cudaGetSymbolAddress((void**)&p_ao, g_ao);

    cpb_kernel<<<(TABLE_SZ + 31) / 32, 256>>>(coords, fc1w, fc1b, fc2w, fc2b);
    bias_expand<<<NHEADS * 64, 256>>>(rpi);

    size_t gemm_smem = (2 * 128 * 20 + 2 * 64 * 20) * sizeof(uint32_t);   // 30.7 KB
    cudaFuncSetAttribute(gemm_qkv_fused, cudaFuncAttributeMaxDynamicSharedMemorySize, (int)gemm_smem);
    cudaFuncSetAttribute(gemm_tc, cudaFuncAttributeMaxDynamicSharedMemorySize, (int)gemm_smem);

    gemm_qkv_fused<<<dim3(768 / 64, (BB * NN) / 128), 256, gemm_smem>>>(
        x, qkv_w, qkv_b, qe, temp);

    {
        size_t smem = 2 * ABUF * sizeof(uint32_t);    // 38.9 KB
        cudaFuncSetAttribute(attn_tc, cudaFuncAttributeMaxDynamicSharedMemorySize, (int)smem);
        attn_tc<<<dim3(16, NHEADS, BB), 128, smem>>>(p_ao);
    }

    gemm_tc<<<dim3(CDIM / 64, (BB * NN) / 128), 256, gemm_smem>>>(
        p_ao, proj_w, proj_b, out, BB * NN, CDIM, CDIM);
}